// round 2
// baseline (speedup 1.0000x reference)
#include <cuda_runtime.h>
#include <math.h>

// ---------------- problem constants ----------------
#define NPTS   74358      // 18 * 27 * 153 == 2 * 243 * 153
#define PK     153
#define PP     17
#define KK2    9
#define CC     128
#define BT1    486        // B*T1 = 2*243

// feature levels
// C_l = {48,96,192,384}, H = {96,48,24,12}, W = {72,36,18,9}
// fT element offsets (channels-last copies)
#define FT_OFF0 0
#define FT_OFF1 5971968
#define FT_OFF2 8957952
#define FT_OFF3 10450944
#define FT_TOTAL 11197440
// weT element offsets ([c][o] layout per level)
#define WT_OFF0 0
#define WT_OFF1 6144
#define WT_OFF2 18432
#define WT_OFF3 43008
#define WT_TOTAL 92160

// output regions (floats)
#define OUT_Q_OFF  0
#define OUT_V_OFF  9517824
#define OUT_SP_OFF 10575360

// ---------------- device scratch (static, allowed) ----------------
__device__ float d_fT[FT_TOTAL];
__device__ float d_weT[WT_TOTAL];
__device__ float d_cwT[1152 * 128];

// ---------------- prep: feature transpose NCHW -> NHWC ----------------
__global__ void tposef_kernel(const float* __restrict__ in, int C, int H, int W, int outOff) {
    __shared__ float tile[32][33];
    int nz = blockIdx.z;
    int n = nz / H, y = nz % H;
    int x0 = blockIdx.x * 32, c0 = blockIdx.y * 32;
    int tx = threadIdx.x, ty = threadIdx.y;
#pragma unroll
    for (int k = 0; k < 4; k++) {
        int c = c0 + ty + 8 * k, x = x0 + tx;
        if (c < C && x < W)
            tile[ty + 8 * k][tx] = in[((size_t)(n * C + c) * H + y) * W + x];
    }
    __syncthreads();
#pragma unroll
    for (int k = 0; k < 4; k++) {
        int x = x0 + ty + 8 * k, c = c0 + tx;
        if (c < C && x < W)
            d_fT[outOff + ((size_t)(n * H + y) * W + x) * C + c] = tile[tx][ty + 8 * k];
    }
}

// ---------------- prep: weight transpose [o][c] -> [c][o] ----------------
__global__ void wtrans_kernel(const float* __restrict__ we, int cl, int off) {
    int e = blockIdx.x * 256 + threadIdx.x;
    if (e < cl * 128) {
        int c = e >> 7, o = e & 127;
        d_weT[off + e] = we[o * cl + c];
    }
}

// conv_w [o][c][k] -> cwT[(k*128+c)][o]
__global__ void cwtrans_kernel(const float* __restrict__ cw) {
    int e = blockIdx.x * 256 + threadIdx.x;
    if (e < 1152 * 128) {
        int i = e >> 7, o = e & 127;
        int c = i & 127, k = i >> 7;
        d_cwT[e] = cw[(o * 128 + c) * 9 + k];
    }
}

// ---------------- sampling positions ----------------
__device__ __forceinline__ float dot4(float4 a, float4 b) {
    return a.x * b.x + a.y * b.y + a.z * b.z + a.w * b.w;
}

__global__ void pos_kernel(const float* __restrict__ query, const float* __restrict__ key,
                           const float* __restrict__ value,
                           const float* __restrict__ w_off, const float* __restrict__ b_off,
                           const float* __restrict__ w_attn, const float* __restrict__ b_attn,
                           float* __restrict__ spo) {
    int w = blockIdx.x * 8 + (threadIdx.x >> 5);
    if (w >= NPTS) return;
    int lane = threadIdx.x & 31;

    const float4* q4 = (const float4*)query;
    const float4* wo4 = (const float4*)w_off;
    float4 qv = q4[(size_t)w * 32 + lane];
    float d0 = dot4(qv, wo4[lane]);
    float d1 = dot4(qv, wo4[32 + lane]);

    int bt1 = w / PK;
    int p = (w % PK) % PP;            // jnp.tile -> pk % 17
    const float4* v4 = (const float4*)value;
    const float4* wa4 = (const float4*)w_attn;
    float4 vv = v4[((size_t)bt1 * PP + p) * 32 + lane];
    float e0 = dot4(vv, wa4[lane]);
    float e1 = dot4(vv, wa4[32 + lane]);

#pragma unroll
    for (int s = 16; s; s >>= 1) {
        d0 += __shfl_xor_sync(0xFFFFFFFFu, d0, s);
        d1 += __shfl_xor_sync(0xFFFFFFFFu, d1, s);
        e0 += __shfl_xor_sync(0xFFFFFFFFu, e0, s);
        e1 += __shfl_xor_sync(0xFFFFFFFFu, e1, s);
    }
    if (lane == 0) {
        float o0 = tanhf(d0 + b_off[0]);
        float o1 = tanhf(d1 + b_off[1]);
        float l0 = e0 + b_attn[0], l1 = e1 + b_attn[1];
        float m = fmaxf(l0, l1);
        float x0 = expf(l0 - m), x1 = expf(l1 - m);
        float inv = 1.0f / (x0 + x1);
        spo[2 * w]     = key[2 * w]     + o0 * (x0 * inv);
        spo[2 * w + 1] = key[2 * w + 1] + o1 * (x1 * inv);
    }
}

// ---------------- main: gather + 4-level 1x1 conv + blend ----------------
template <int CL, int H, int W>
__device__ __forceinline__ void do_level(int qb, int t, float4* gsm,
                                         float4& acc0, float4& acc1,
                                         int ftOff4, int wtOff4,
                                         const float* __restrict__ sp) {
    // --- gather: 16 threads per point ---
    {
        int pt = t >> 4, ci = t & 15;
        int q = qb + pt;
        float w00 = 0.f, w01 = 0.f, w10 = 0.f, w11 = 0.f;
        int o00 = 0, o01 = 0, o10 = 0, o11 = 0;
        if (q < NPTS) {
            float gx = __ldg(&sp[2 * q]);
            float gy = __ldg(&sp[2 * q + 1]);
            float ix = ((gx + 1.f) * (float)W - 1.f) * 0.5f;
            float iy = ((gy + 1.f) * (float)H - 1.f) * 0.5f;
            float fx = floorf(ix), fy = floorf(iy);
            int x0 = (int)fx, y0 = (int)fy;
            float wx1 = ix - fx, wy1 = iy - fy;
            float wx0 = 1.f - wx1, wy0 = 1.f - wy1;
            int n = q / 4131;  // 27*153
            int base = ftOff4 + n * (H * W * (CL / 4));
            bool vx0 = (unsigned)x0 < (unsigned)W;
            bool vx1 = (unsigned)(x0 + 1) < (unsigned)W;
            bool vy0 = (unsigned)y0 < (unsigned)H;
            bool vy1 = (unsigned)(y0 + 1) < (unsigned)H;
            int r0 = y0 * W, r1 = r0 + W;
            if (vy0 && vx0) { o00 = base + (r0 + x0) * (CL / 4);     w00 = wy0 * wx0; }
            if (vy0 && vx1) { o01 = base + (r0 + x0 + 1) * (CL / 4); w01 = wy0 * wx1; }
            if (vy1 && vx0) { o10 = base + (r1 + x0) * (CL / 4);     w10 = wy1 * wx0; }
            if (vy1 && vx1) { o11 = base + (r1 + x0 + 1) * (CL / 4); w11 = wy1 * wx1; }
        }
        const float4* f4 = (const float4*)d_fT;
        for (int c4 = ci; c4 < CL / 4; c4 += 16) {
            float4 a = f4[o00 + c4], b = f4[o01 + c4];
            float4 c = f4[o10 + c4], d = f4[o11 + c4];
            float4 g;
            g.x = w00 * a.x + w01 * b.x + w10 * c.x + w11 * d.x;
            g.y = w00 * a.y + w01 * b.y + w10 * c.y + w11 * d.y;
            g.z = w00 * a.z + w01 * b.z + w10 * c.z + w11 * d.z;
            g.w = w00 * a.w + w01 * b.w + w10 * c.w + w11 * d.w;
            gsm[pt * 96 + c4] = g;
        }
    }
    __syncthreads();
    // --- GEMM: thread = 4 outputs x 2 points ---
    {
        int lane = t & 31;
        int pb = (t >> 5) * 2;
        const float4* w4 = ((const float4*)d_weT) + wtOff4;
#pragma unroll 2
        for (int c4 = 0; c4 < CL / 4; c4++) {
            float4 w0 = w4[(c4 * 4 + 0) * 32 + lane];
            float4 w1 = w4[(c4 * 4 + 1) * 32 + lane];
            float4 w2 = w4[(c4 * 4 + 2) * 32 + lane];
            float4 w3 = w4[(c4 * 4 + 3) * 32 + lane];
            float4 ga = gsm[pb * 96 + c4];
            float4 gb = gsm[(pb + 1) * 96 + c4];
            acc0.x = fmaf(ga.x, w0.x, fmaf(ga.y, w1.x, fmaf(ga.z, w2.x, fmaf(ga.w, w3.x, acc0.x))));
            acc0.y = fmaf(ga.x, w0.y, fmaf(ga.y, w1.y, fmaf(ga.z, w2.y, fmaf(ga.w, w3.y, acc0.y))));
            acc0.z = fmaf(ga.x, w0.z, fmaf(ga.y, w1.z, fmaf(ga.z, w2.z, fmaf(ga.w, w3.z, acc0.z))));
            acc0.w = fmaf(ga.x, w0.w, fmaf(ga.y, w1.w, fmaf(ga.z, w2.w, fmaf(ga.w, w3.w, acc0.w))));
            acc1.x = fmaf(gb.x, w0.x, fmaf(gb.y, w1.x, fmaf(gb.z, w2.x, fmaf(gb.w, w3.x, acc1.x))));
            acc1.y = fmaf(gb.x, w0.y, fmaf(gb.y, w1.y, fmaf(gb.z, w2.y, fmaf(gb.w, w3.y, acc1.y))));
            acc1.z = fmaf(gb.x, w0.z, fmaf(gb.y, w1.z, fmaf(gb.z, w2.z, fmaf(gb.w, w3.z, acc1.z))));
            acc1.w = fmaf(gb.x, w0.w, fmaf(gb.y, w1.w, fmaf(gb.z, w2.w, fmaf(gb.w, w3.w, acc1.w))));
        }
    }
    __syncthreads();
}

__global__ void __launch_bounds__(256) main_kernel(
    const float* __restrict__ sp, const float* __restrict__ query,
    const float* __restrict__ be0, const float* __restrict__ be1,
    const float* __restrict__ be2, const float* __restrict__ be3,
    float* __restrict__ outq) {
    __shared__ float4 gsm[16 * 96];
    int t = threadIdx.x;
    int qb = blockIdx.x * 16;
    float4 acc0 = make_float4(0.f, 0.f, 0.f, 0.f);
    float4 acc1 = make_float4(0.f, 0.f, 0.f, 0.f);

    do_level<48, 96, 72>(qb, t, gsm, acc0, acc1, FT_OFF0 / 4, WT_OFF0 / 4, sp);
    do_level<96, 48, 36>(qb, t, gsm, acc0, acc1, FT_OFF1 / 4, WT_OFF1 / 4, sp);
    do_level<192, 24, 18>(qb, t, gsm, acc0, acc1, FT_OFF2 / 4, WT_OFF2 / 4, sp);
    do_level<384, 12, 9>(qb, t, gsm, acc0, acc1, FT_OFF3 / 4, WT_OFF3 / 4, sp);

    int lane = t & 31;
    int pb = (t >> 5) * 2;
    const float4* b04 = (const float4*)be0;
    const float4* b14 = (const float4*)be1;
    const float4* b24 = (const float4*)be2;
    const float4* b34 = (const float4*)be3;
    float4 v0 = b04[lane], v1 = b14[lane], v2 = b24[lane], v3 = b34[lane];
    float4 bs;
    bs.x = 0.025f * (v0.x + v1.x + v2.x + v3.x);
    bs.y = 0.025f * (v0.y + v1.y + v2.y + v3.y);
    bs.z = 0.025f * (v0.z + v1.z + v2.z + v3.z);
    bs.w = 0.025f * (v0.w + v1.w + v2.w + v3.w);

    const float4* q4 = (const float4*)query;
    float4* oq4 = (float4*)outq;
#pragma unroll
    for (int j = 0; j < 2; j++) {
        int q = qb + pb + j;
        if (q < NPTS) {
            float4 a = (j == 0) ? acc0 : acc1;
            float4 qv = q4[(size_t)q * 32 + lane];
            float4 r;
            r.x = 0.025f * a.x + bs.x + 0.9f * qv.x;
            r.y = 0.025f * a.y + bs.y + 0.9f * qv.y;
            r.z = 0.025f * a.z + bs.z + 0.9f * qv.z;
            r.w = 0.025f * a.w + bs.w + 0.9f * qv.w;
            oq4[(size_t)q * 32 + lane] = r;
        }
    }
}

// ---------------- final conv: [b,t1] x (1152 -> 128) per p ----------------
// x reshaped (p, k, c): output p consumes 9 contiguous rows (p*9..p*9+8) of
// 128 floats => 288 contiguous float4 starting at p*288.
__global__ void __launch_bounds__(256) conv_kernel(const float* __restrict__ nq,
                                                   const float* __restrict__ conv_b,
                                                   float* __restrict__ nv) {
    extern __shared__ float xs[];
    int bi = blockIdx.x;  // 0..485
    int t = threadIdx.x;
    const float4* src = (const float4*)(nq + (size_t)bi * PK * CC);
    float4* xs4 = (float4*)xs;
    for (int i = t; i < PK * 32; i += 256) xs4[i] = src[i];
    __syncthreads();

    int o = t & 127;
    int half = t >> 7;
    int p0 = half * 9;
    float acc[9];
#pragma unroll
    for (int j = 0; j < 9; j++) acc[j] = 0.f;

    // precompute clamped row bases (p=17 for half=1,j=8 is invalid -> clamp to 0, never stored)
    int pbase[9];
#pragma unroll
    for (int j = 0; j < 9; j++) {
        int p = p0 + j;
        pbase[j] = (p < PP) ? p * 288 : 0;
    }

    for (int i4 = 0; i4 < 288; i4++) {
        int i = i4 * 4;
        float w0 = d_cwT[(i + 0) * 128 + o];
        float w1 = d_cwT[(i + 1) * 128 + o];
        float w2 = d_cwT[(i + 2) * 128 + o];
        float w3 = d_cwT[(i + 3) * 128 + o];
#pragma unroll
        for (int j = 0; j < 9; j++) {
            float4 x = xs4[pbase[j] + i4];
            acc[j] = fmaf(x.x, w0, acc[j]);
            acc[j] = fmaf(x.y, w1, acc[j]);
            acc[j] = fmaf(x.z, w2, acc[j]);
            acc[j] = fmaf(x.w, w3, acc[j]);
        }
    }
    float cb = conv_b[o];
#pragma unroll
    for (int j = 0; j < 9; j++) {
        int p = p0 + j;
        if (p < PP) nv[((size_t)bi * PP + p) * 128 + o] = acc[j] + cb;
    }
}

// ---------------- launch ----------------
extern "C" void kernel_launch(void* const* d_in, const int* in_sizes, int n_in,
                              void* d_out, int out_size) {
    const float* f0     = (const float*)d_in[0];
    const float* f1     = (const float*)d_in[1];
    const float* f2     = (const float*)d_in[2];
    const float* f3     = (const float*)d_in[3];
    const float* query  = (const float*)d_in[4];
    const float* key    = (const float*)d_in[5];
    const float* value  = (const float*)d_in[6];
    const float* w_off  = (const float*)d_in[7];
    const float* b_off  = (const float*)d_in[8];
    const float* w_attn = (const float*)d_in[9];
    const float* b_attn = (const float*)d_in[10];
    const float* we0    = (const float*)d_in[11];
    const float* be0    = (const float*)d_in[12];
    const float* we1    = (const float*)d_in[13];
    const float* be1    = (const float*)d_in[14];
    const float* we2    = (const float*)d_in[15];
    const float* be2    = (const float*)d_in[16];
    const float* we3    = (const float*)d_in[17];
    const float* be3    = (const float*)d_in[18];
    const float* conv_w = (const float*)d_in[19];
    const float* conv_b = (const float*)d_in[20];

    float* out   = (float*)d_out;
    float* outQ  = out + OUT_Q_OFF;
    float* outV  = out + OUT_V_OFF;
    float* outSP = out + OUT_SP_OFF;

    dim3 tb(32, 8);
    tposef_kernel<<<dim3(3, 2, 18 * 96), tb>>>(f0, 48, 96, 72, FT_OFF0);
    tposef_kernel<<<dim3(2, 3, 18 * 48), tb>>>(f1, 96, 48, 36, FT_OFF1);
    tposef_kernel<<<dim3(1, 6, 18 * 24), tb>>>(f2, 192, 24, 18, FT_OFF2);
    tposef_kernel<<<dim3(1, 12, 18 * 12), tb>>>(f3, 384, 12, 9, FT_OFF3);

    wtrans_kernel<<<(48 * 128 + 255) / 256, 256>>>(we0, 48, WT_OFF0);
    wtrans_kernel<<<(96 * 128 + 255) / 256, 256>>>(we1, 96, WT_OFF1);
    wtrans_kernel<<<(192 * 128 + 255) / 256, 256>>>(we2, 192, WT_OFF2);
    wtrans_kernel<<<(384 * 128 + 255) / 256, 256>>>(we3, 384, WT_OFF3);
    cwtrans_kernel<<<576, 256>>>(conv_w);

    pos_kernel<<<9295, 256>>>(query, key, value, w_off, b_off, w_attn, b_attn, outSP);

    main_kernel<<<4648, 256>>>(outSP, query, be0, be1, be2, be3, outQ);

    cudaFuncSetAttribute(conv_kernel, cudaFuncAttributeMaxDynamicSharedMemorySize, 78336);
    conv_kernel<<<486, 256, 78336>>>(outQ, conv_b, outV);
}

// round 4
// speedup vs baseline: 1.3711x; 1.3711x over previous
#include <cuda_runtime.h>
#include <math.h>
#include <stdint.h>

// ---------------- problem constants ----------------
#define NPTS   74358      // 18 * 27 * 153 == 2 * 243 * 153
#define PK     153
#define PP     17
#define CC     128
#define BT1    486

// feature levels: C_l = {48,96,192,384}, H = {96,48,24,12}, W = {72,36,18,9}
#define FT_OFF0 0
#define FT_OFF1 5971968
#define FT_OFF2 8957952
#define FT_OFF3 10450944
#define FT_TOTAL 11197440
#define WT_OFF0 0
#define WT_OFF1 6144
#define WT_OFF2 18432
#define WT_OFF3 43008
#define WT_TOTAL 92160

// output regions (floats)
#define OUT_Q_OFF  0
#define OUT_V_OFF  9517824
#define OUT_SP_OFF 10575360

// main-kernel tiling
#define PTS_PER_BLK 64
#define GSM_STRIDE  66          // words per channel row (even, conflict-free)
#define GSM_BYTES   (384 * GSM_STRIDE * 4)   // 101376 B

// ---------------- device scratch ----------------
__device__ float d_fT[FT_TOTAL];
__device__ float d_weT[WT_TOTAL];
__device__ float d_cwT[1152 * 128];

// ---------------- f32x2 helpers ----------------
__device__ __forceinline__ void fma2(unsigned long long& d, unsigned long long a,
                                     unsigned long long b) {
    asm("fma.rn.f32x2 %0, %1, %2, %0;" : "+l"(d) : "l"(a), "l"(b));
}
__device__ __forceinline__ unsigned long long bcast2(float w) {
    unsigned long long r;
    unsigned int wi = __float_as_uint(w);
    asm("mov.b64 %0, {%1, %1};" : "=l"(r) : "r"(wi));
    return r;
}
__device__ __forceinline__ float lo2(unsigned long long v) {
    return __uint_as_float((unsigned int)v);
}
__device__ __forceinline__ float hi2(unsigned long long v) {
    return __uint_as_float((unsigned int)(v >> 32));
}

// ---------------- prep: feature transpose NCHW -> NHWC ----------------
__global__ void tposef_kernel(const float* __restrict__ in, int C, int H, int W, int outOff) {
    __shared__ float tile[32][33];
    int nz = blockIdx.z;
    int n = nz / H, y = nz % H;
    int x0 = blockIdx.x * 32, c0 = blockIdx.y * 32;
    int tx = threadIdx.x, ty = threadIdx.y;
#pragma unroll
    for (int k = 0; k < 4; k++) {
        int c = c0 + ty + 8 * k, x = x0 + tx;
        if (c < C && x < W)
            tile[ty + 8 * k][tx] = in[((size_t)(n * C + c) * H + y) * W + x];
    }
    __syncthreads();
#pragma unroll
    for (int k = 0; k < 4; k++) {
        int x = x0 + ty + 8 * k, c = c0 + tx;
        if (c < C && x < W)
            d_fT[outOff + ((size_t)(n * H + y) * W + x) * C + c] = tile[tx][ty + 8 * k];
    }
}

// ---------------- prep: weight transpose [o][c] -> [c][o] ----------------
__global__ void wtrans_kernel(const float* __restrict__ we, int cl, int off) {
    int e = blockIdx.x * 256 + threadIdx.x;
    if (e < cl * 128) {
        int c = e >> 7, o = e & 127;
        d_weT[off + e] = we[o * cl + c];
    }
}

__global__ void cwtrans_kernel(const float* __restrict__ cw) {
    int e = blockIdx.x * 256 + threadIdx.x;
    if (e < 1152 * 128) {
        int i = e >> 7, o = e & 127;
        int c = i & 127, k = i >> 7;
        d_cwT[e] = cw[(o * 128 + c) * 9 + k];
    }
}

// ---------------- sampling positions ----------------
__device__ __forceinline__ float dot4(float4 a, float4 b) {
    return a.x * b.x + a.y * b.y + a.z * b.z + a.w * b.w;
}

__global__ void pos_kernel(const float* __restrict__ query, const float* __restrict__ key,
                           const float* __restrict__ value,
                           const float* __restrict__ w_off, const float* __restrict__ b_off,
                           const float* __restrict__ w_attn, const float* __restrict__ b_attn,
                           float* __restrict__ spo) {
    int w = blockIdx.x * 8 + (threadIdx.x >> 5);
    if (w >= NPTS) return;
    int lane = threadIdx.x & 31;

    const float4* q4 = (const float4*)query;
    const float4* wo4 = (const float4*)w_off;
    float4 qv = q4[(size_t)w * 32 + lane];
    float d0 = dot4(qv, wo4[lane]);
    float d1 = dot4(qv, wo4[32 + lane]);

    int bt1 = w / PK;
    int p = (w % PK) % PP;
    const float4* v4 = (const float4*)value;
    const float4* wa4 = (const float4*)w_attn;
    float4 vv = v4[((size_t)bt1 * PP + p) * 32 + lane];
    float e0 = dot4(vv, wa4[lane]);
    float e1 = dot4(vv, wa4[32 + lane]);

#pragma unroll
    for (int s = 16; s; s >>= 1) {
        d0 += __shfl_xor_sync(0xFFFFFFFFu, d0, s);
        d1 += __shfl_xor_sync(0xFFFFFFFFu, d1, s);
        e0 += __shfl_xor_sync(0xFFFFFFFFu, e0, s);
        e1 += __shfl_xor_sync(0xFFFFFFFFu, e1, s);
    }
    if (lane == 0) {
        float o0 = tanhf(d0 + b_off[0]);
        float o1 = tanhf(d1 + b_off[1]);
        float l0 = e0 + b_attn[0], l1 = e1 + b_attn[1];
        float m = fmaxf(l0, l1);
        float x0 = expf(l0 - m), x1 = expf(l1 - m);
        float inv = 1.0f / (x0 + x1);
        spo[2 * w]     = key[2 * w]     + o0 * (x0 * inv);
        spo[2 * w + 1] = key[2 * w + 1] + o1 * (x1 * inv);
    }
}

// ---------------- main: gather + 4-level 1x1 conv + blend ----------------
// gsm layout: [channel][point] floats, row stride GSM_STRIDE (66 words):
//   - gather STS conflict-free (banks = 8*ci + 2*j + pt, disjoint per lane group)
//   - GEMM reads broadcast float2 pairs (pt even offsets, 8B aligned)
template <int CL, int H, int W>
__device__ __forceinline__ void do_level(int qb, int t, float* gsm,
                                         unsigned long long acc[4][4],
                                         int ftOff4, int wtOff4,
                                         const float* __restrict__ sp) {
    // --- gather: 4 threads per point, lanes -> channels (coalesced LDG) ---
    {
        int pt = t >> 2, ci = t & 3;
        int q = qb + pt;
        float w00 = 0.f, w01 = 0.f, w10 = 0.f, w11 = 0.f;
        int o00 = 0, o01 = 0, o10 = 0, o11 = 0;
        if (q < NPTS) {
            float gx = __ldg(&sp[2 * q]);
            float gy = __ldg(&sp[2 * q + 1]);
            float ix = ((gx + 1.f) * (float)W - 1.f) * 0.5f;
            float iy = ((gy + 1.f) * (float)H - 1.f) * 0.5f;
            float fx = floorf(ix), fy = floorf(iy);
            int x0 = (int)fx, y0 = (int)fy;
            float wx1 = ix - fx, wy1 = iy - fy;
            float wx0 = 1.f - wx1, wy0 = 1.f - wy1;
            int n = q / 4131;  // 27*153
            int base = ftOff4 + n * (H * W * (CL / 4));
            bool vx0 = (unsigned)x0 < (unsigned)W;
            bool vx1 = (unsigned)(x0 + 1) < (unsigned)W;
            bool vy0 = (unsigned)y0 < (unsigned)H;
            bool vy1 = (unsigned)(y0 + 1) < (unsigned)H;
            int r0 = y0 * W, r1 = r0 + W;
            if (vy0 && vx0) { o00 = base + (r0 + x0) * (CL / 4);     w00 = wy0 * wx0; }
            if (vy0 && vx1) { o01 = base + (r0 + x0 + 1) * (CL / 4); w01 = wy0 * wx1; }
            if (vy1 && vx0) { o10 = base + (r1 + x0) * (CL / 4);     w10 = wy1 * wx0; }
            if (vy1 && vx1) { o11 = base + (r1 + x0 + 1) * (CL / 4); w11 = wy1 * wx1; }
        }
        const float4* f4 = (const float4*)d_fT;
#pragma unroll 3
        for (int c4 = ci; c4 < CL / 4; c4 += 4) {
            float4 a = f4[o00 + c4], b = f4[o01 + c4];
            float4 c = f4[o10 + c4], d = f4[o11 + c4];
            float gx0 = w00 * a.x + w01 * b.x + w10 * c.x + w11 * d.x;
            float gy0 = w00 * a.y + w01 * b.y + w10 * c.y + w11 * d.y;
            float gz0 = w00 * a.z + w01 * b.z + w10 * c.z + w11 * d.z;
            float gw0 = w00 * a.w + w01 * b.w + w10 * c.w + w11 * d.w;
            int cb = 4 * c4;
            gsm[(cb + 0) * GSM_STRIDE + pt] = gx0;
            gsm[(cb + 1) * GSM_STRIDE + pt] = gy0;
            gsm[(cb + 2) * GSM_STRIDE + pt] = gz0;
            gsm[(cb + 3) * GSM_STRIDE + pt] = gw0;
        }
    }
    __syncthreads();
    // --- GEMM: warp w -> points 8w..8w+7; lane -> outputs 4lane..4lane+3 ---
    {
        int lane = t & 31;
        int w = t >> 5;
        int pbase = w * 8;
        const float4* w4 = ((const float4*)d_weT) + wtOff4;
        const float2* gs2 = (const float2*)gsm;  // word idx / 2
#pragma unroll 2
        for (int c4 = 0; c4 < CL / 4; c4++) {
#pragma unroll
            for (int j = 0; j < 4; j++) {
                int c = 4 * c4 + j;
                float4 wj = w4[c * 32 + lane];
                unsigned long long wp0 = bcast2(wj.x);
                unsigned long long wp1 = bcast2(wj.y);
                unsigned long long wp2 = bcast2(wj.z);
                unsigned long long wp3 = bcast2(wj.w);
                int gbase2 = (c * GSM_STRIDE + pbase) >> 1;
#pragma unroll
                for (int pr = 0; pr < 4; pr++) {
                    float2 gf = gs2[gbase2 + pr];
                    unsigned long long g;
                    memcpy(&g, &gf, 8);
                    fma2(acc[0][pr], g, wp0);
                    fma2(acc[1][pr], g, wp1);
                    fma2(acc[2][pr], g, wp2);
                    fma2(acc[3][pr], g, wp3);
                }
            }
        }
    }
    __syncthreads();
}

__global__ void __launch_bounds__(256) main_kernel(
    const float* __restrict__ sp, const float* __restrict__ query,
    const float* __restrict__ be0, const float* __restrict__ be1,
    const float* __restrict__ be2, const float* __restrict__ be3,
    float* __restrict__ outq) {
    extern __shared__ float gsm[];
    int t = threadIdx.x;
    int qb = blockIdx.x * PTS_PER_BLK;

    unsigned long long acc[4][4];
#pragma unroll
    for (int k = 0; k < 4; k++)
#pragma unroll
        for (int pr = 0; pr < 4; pr++) acc[k][pr] = 0ull;

    do_level<48, 96, 72>(qb, t, gsm, acc, FT_OFF0 / 4, WT_OFF0 / 4, sp);
    do_level<96, 48, 36>(qb, t, gsm, acc, FT_OFF1 / 4, WT_OFF1 / 4, sp);
    do_level<192, 24, 18>(qb, t, gsm, acc, FT_OFF2 / 4, WT_OFF2 / 4, sp);
    do_level<384, 12, 9>(qb, t, gsm, acc, FT_OFF3 / 4, WT_OFF3 / 4, sp);

    int lane = t & 31;
    int w = t >> 5;
    const float4* b04 = (const float4*)be0;
    const float4* b14 = (const float4*)be1;
    const float4* b24 = (const float4*)be2;
    const float4* b34 = (const float4*)be3;
    float4 v0 = b04[lane], v1 = b14[lane], v2 = b24[lane], v3 = b34[lane];
    float4 bs;
    bs.x = 0.025f * (v0.x + v1.x + v2.x + v3.x);
    bs.y = 0.025f * (v0.y + v1.y + v2.y + v3.y);
    bs.z = 0.025f * (v0.z + v1.z + v2.z + v3.z);
    bs.w = 0.025f * (v0.w + v1.w + v2.w + v3.w);

    const float4* q4 = (const float4*)query;
    float4* oq4 = (float4*)outq;
#pragma unroll
    for (int pr = 0; pr < 4; pr++) {
#pragma unroll
        for (int h = 0; h < 2; h++) {
            int q = qb + w * 8 + 2 * pr + h;
            if (q < NPTS) {
                float a0 = h ? hi2(acc[0][pr]) : lo2(acc[0][pr]);
                float a1 = h ? hi2(acc[1][pr]) : lo2(acc[1][pr]);
                float a2 = h ? hi2(acc[2][pr]) : lo2(acc[2][pr]);
                float a3 = h ? hi2(acc[3][pr]) : lo2(acc[3][pr]);
                float4 qv = q4[(size_t)q * 32 + lane];
                float4 r;
                r.x = 0.025f * a0 + bs.x + 0.9f * qv.x;
                r.y = 0.025f * a1 + bs.y + 0.9f * qv.y;
                r.z = 0.025f * a2 + bs.z + 0.9f * qv.z;
                r.w = 0.025f * a3 + bs.w + 0.9f * qv.w;
                oq4[(size_t)q * 32 + lane] = r;
            }
        }
    }
}

// ---------------- final conv: [b,t1] x (1152 -> 128) per p ----------------
__global__ void __launch_bounds__(256) conv_kernel(const float* __restrict__ nq,
                                                   const float* __restrict__ conv_b,
                                                   float* __restrict__ nv) {
    extern __shared__ float xs[];
    int bi = blockIdx.x;  // 0..485
    int t = threadIdx.x;
    const float4* src = (const float4*)(nq + (size_t)bi * PK * CC);
    float4* xs4 = (float4*)xs;
    for (int i = t; i < PK * 32; i += 256) xs4[i] = src[i];
    __syncthreads();

    int o = t & 127;
    int half = t >> 7;
    int p0 = half * 9;
    float acc[9];
#pragma unroll
    for (int j = 0; j < 9; j++) acc[j] = 0.f;

    int pbase[9];
#pragma unroll
    for (int j = 0; j < 9; j++) {
        int p = p0 + j;
        pbase[j] = (p < PP) ? p * 288 : 0;   // clamp, never stored
    }

    for (int i4 = 0; i4 < 288; i4++) {
        int i = i4 * 4;
        float w0 = d_cwT[(i + 0) * 128 + o];
        float w1 = d_cwT[(i + 1) * 128 + o];
        float w2 = d_cwT[(i + 2) * 128 + o];
        float w3 = d_cwT[(i + 3) * 128 + o];
#pragma unroll
        for (int j = 0; j < 9; j++) {
            float4 x = xs4[pbase[j] + i4];
            acc[j] = fmaf(x.x, w0, acc[j]);
            acc[j] = fmaf(x.y, w1, acc[j]);
            acc[j] = fmaf(x.z, w2, acc[j]);
            acc[j] = fmaf(x.w, w3, acc[j]);
        }
    }
    float cb = conv_b[o];
#pragma unroll
    for (int j = 0; j < 9; j++) {
        int p = p0 + j;
        if (p < PP) nv[((size_t)bi * PP + p) * 128 + o] = acc[j] + cb;
    }
}

// ---------------- launch ----------------
extern "C" void kernel_launch(void* const* d_in, const int* in_sizes, int n_in,
                              void* d_out, int out_size) {
    const float* f0     = (const float*)d_in[0];
    const float* f1     = (const float*)d_in[1];
    const float* f2     = (const float*)d_in[2];
    const float* f3     = (const float*)d_in[3];
    const float* query  = (const float*)d_in[4];
    const float* key    = (const float*)d_in[5];
    const float* value  = (const float*)d_in[6];
    const float* w_off  = (const float*)d_in[7];
    const float* b_off  = (const float*)d_in[8];
    const float* w_attn = (const float*)d_in[9];
    const float* b_attn = (const float*)d_in[10];
    const float* we0    = (const float*)d_in[11];
    const float* be0    = (const float*)d_in[12];
    const float* we1    = (const float*)d_in[13];
    const float* be1    = (const float*)d_in[14];
    const float* we2    = (const float*)d_in[15];
    const float* be2    = (const float*)d_in[16];
    const float* we3    = (const float*)d_in[17];
    const float* be3    = (const float*)d_in[18];
    const float* conv_w = (const float*)d_in[19];
    const float* conv_b = (const float*)d_in[20];

    float* out   = (float*)d_out;
    float* outQ  = out + OUT_Q_OFF;
    float* outV  = out + OUT_V_OFF;
    float* outSP = out + OUT_SP_OFF;

    dim3 tb(32, 8);
    tposef_kernel<<<dim3(3, 2, 18 * 96), tb>>>(f0, 48, 96, 72, FT_OFF0);
    tposef_kernel<<<dim3(2, 3, 18 * 48), tb>>>(f1, 96, 48, 36, FT_OFF1);
    tposef_kernel<<<dim3(1, 6, 18 * 24), tb>>>(f2, 192, 24, 18, FT_OFF2);
    tposef_kernel<<<dim3(1, 12, 18 * 12), tb>>>(f3, 384, 12, 9, FT_OFF3);

    wtrans_kernel<<<(48 * 128 + 255) / 256, 256>>>(we0, 48, WT_OFF0);
    wtrans_kernel<<<(96 * 128 + 255) / 256, 256>>>(we1, 96, WT_OFF1);
    wtrans_kernel<<<(192 * 128 + 255) / 256, 256>>>(we2, 192, WT_OFF2);
    wtrans_kernel<<<(384 * 128 + 255) / 256, 256>>>(we3, 384, WT_OFF3);
    cwtrans_kernel<<<576, 256>>>(conv_w);

    pos_kernel<<<9295, 256>>>(query, key, value, w_off, b_off, w_attn, b_attn, outSP);

    cudaFuncSetAttribute(main_kernel, cudaFuncAttributeMaxDynamicSharedMemorySize, GSM_BYTES);
    main_kernel<<<(NPTS + PTS_PER_BLK - 1) / PTS_PER_BLK, 256, GSM_BYTES>>>(
        outSP, query, be0, be1, be2, be3, outQ);

    cudaFuncSetAttribute(conv_kernel, cudaFuncAttributeMaxDynamicSharedMemorySize, 78336);
    conv_kernel<<<486, 256, 78336>>>(outQ, conv_b, outV);
}

// round 6
// speedup vs baseline: 1.3904x; 1.0140x over previous
#include <cuda_runtime.h>
#include <math.h>
#include <stdint.h>

// ---------------- problem constants ----------------
#define NPTS   74358      // 18 * 27 * 153 == 2 * 243 * 153
#define PK     153
#define PP     17
#define CC     128
#define BT1    486

// feature levels: C_l = {48,96,192,384}, H = {96,48,24,12}, W = {72,36,18,9}
#define FT_OFF0 0
#define FT_OFF1 5971968
#define FT_OFF2 8957952
#define FT_OFF3 10450944
#define FT_TOTAL 11197440
#define WT_TOTAL 92160          // 720 * 128, channel-major [c][o]

// output regions (floats)
#define OUT_Q_OFF  0
#define OUT_V_OFF  9517824
#define OUT_SP_OFF 10575360

// main-kernel tiling
#define PTS_PER_BLK 64
#define CHUNK   16              // channels per pipeline chunk
#define NCHUNK  45              // 720 / 16
#define GSTRIDE 66              // words per channel row in smem buffer

// ---------------- device scratch ----------------
__device__ float d_fT[FT_TOTAL];
__device__ float d_weT[WT_TOTAL];   // [global_channel 0..719][out 0..127]
__device__ float d_cwT[1152 * 128];

// ---------------- f32x2 helpers ----------------
__device__ __forceinline__ void fma2(unsigned long long& d, unsigned long long a,
                                     unsigned long long b) {
    asm("fma.rn.f32x2 %0, %1, %2, %0;" : "+l"(d) : "l"(a), "l"(b));
}
__device__ __forceinline__ unsigned long long bcast2(float w) {
    unsigned long long r;
    unsigned int wi = __float_as_uint(w);
    asm("mov.b64 %0, {%1, %1};" : "=l"(r) : "r"(wi));
    return r;
}
__device__ __forceinline__ float lo2(unsigned long long v) {
    return __uint_as_float((unsigned int)v);
}
__device__ __forceinline__ float hi2(unsigned long long v) {
    return __uint_as_float((unsigned int)(v >> 32));
}

// ---------------- prep: feature transpose NCHW -> NHWC ----------------
__global__ void tposef_kernel(const float* __restrict__ in, int C, int H, int W, int outOff) {
    __shared__ float tile[32][33];
    int nz = blockIdx.z;
    int n = nz / H, y = nz % H;
    int x0 = blockIdx.x * 32, c0 = blockIdx.y * 32;
    int tx = threadIdx.x, ty = threadIdx.y;
#pragma unroll
    for (int k = 0; k < 4; k++) {
        int c = c0 + ty + 8 * k, x = x0 + tx;
        if (c < C && x < W)
            tile[ty + 8 * k][tx] = in[((size_t)(n * C + c) * H + y) * W + x];
    }
    __syncthreads();
#pragma unroll
    for (int k = 0; k < 4; k++) {
        int x = x0 + ty + 8 * k, c = c0 + tx;
        if (c < C && x < W)
            d_fT[outOff + ((size_t)(n * H + y) * W + x) * C + c] = tile[tx][ty + 8 * k];
    }
}

// ---------------- prep: weight transpose [o][c] -> [c][o] ----------------
__global__ void wtrans_kernel(const float* __restrict__ we, int cl, int off) {
    int e = blockIdx.x * 256 + threadIdx.x;
    if (e < cl * 128) {
        int c = e >> 7, o = e & 127;
        d_weT[off + e] = we[o * cl + c];
    }
}

__global__ void cwtrans_kernel(const float* __restrict__ cw) {
    int e = blockIdx.x * 256 + threadIdx.x;
    if (e < 1152 * 128) {
        int i = e >> 7, o = e & 127;
        int c = i & 127, k = i >> 7;
        d_cwT[e] = cw[(o * 128 + c) * 9 + k];
    }
}

// ---------------- sampling positions ----------------
__device__ __forceinline__ float dot4(float4 a, float4 b) {
    return a.x * b.x + a.y * b.y + a.z * b.z + a.w * b.w;
}

__global__ void pos_kernel(const float* __restrict__ query, const float* __restrict__ key,
                           const float* __restrict__ value,
                           const float* __restrict__ w_off, const float* __restrict__ b_off,
                           const float* __restrict__ w_attn, const float* __restrict__ b_attn,
                           float* __restrict__ spo) {
    int w = blockIdx.x * 8 + (threadIdx.x >> 5);
    if (w >= NPTS) return;
    int lane = threadIdx.x & 31;

    const float4* q4 = (const float4*)query;
    const float4* wo4 = (const float4*)w_off;
    float4 qv = q4[(size_t)w * 32 + lane];
    float d0 = dot4(qv, wo4[lane]);
    float d1 = dot4(qv, wo4[32 + lane]);

    int bt1 = w / PK;
    int p = (w % PK) % PP;
    const float4* v4 = (const float4*)value;
    const float4* wa4 = (const float4*)w_attn;
    float4 vv = v4[((size_t)bt1 * PP + p) * 32 + lane];
    float e0 = dot4(vv, wa4[lane]);
    float e1 = dot4(vv, wa4[32 + lane]);

#pragma unroll
    for (int s = 16; s; s >>= 1) {
        d0 += __shfl_xor_sync(0xFFFFFFFFu, d0, s);
        d1 += __shfl_xor_sync(0xFFFFFFFFu, d1, s);
        e0 += __shfl_xor_sync(0xFFFFFFFFu, e0, s);
        e1 += __shfl_xor_sync(0xFFFFFFFFu, e1, s);
    }
    if (lane == 0) {
        float o0 = tanhf(d0 + b_off[0]);
        float o1 = tanhf(d1 + b_off[1]);
        float l0 = e0 + b_attn[0], l1 = e1 + b_attn[1];
        float m = fmaxf(l0, l1);
        float x0 = expf(l0 - m), x1 = expf(l1 - m);
        float inv = 1.0f / (x0 + x1);
        spo[2 * w]     = key[2 * w]     + o0 * (x0 * inv);
        spo[2 * w + 1] = key[2 * w + 1] + o1 * (x1 * inv);
    }
}

// ---------------- bilinear geometry per level ----------------
__device__ __forceinline__ void setgeom(bool valid, float gx, float gy, int n, int lvl,
                                        int& lf, float& w00, float& w01, float& w10, float& w11,
                                        int& o00, int& o01, int& o10, int& o11) {
    const int Hs[4]  = {96, 48, 24, 12};
    const int Ws[4]  = {72, 36, 18, 9};
    const int C4s[4] = {12, 24, 48, 96};
    const int FO4[4] = {FT_OFF0 / 4, FT_OFF1 / 4, FT_OFF2 / 4, FT_OFF3 / 4};
    const int LFs[4] = {0, 3, 9, 21};
    lf = LFs[lvl];
    w00 = w01 = w10 = w11 = 0.f;
    o00 = o01 = o10 = o11 = 0;
    if (!valid) return;
    int H = Hs[lvl], W = Ws[lvl], c4 = C4s[lvl];
    float ix = ((gx + 1.f) * (float)W - 1.f) * 0.5f;
    float iy = ((gy + 1.f) * (float)H - 1.f) * 0.5f;
    float fx = floorf(ix), fy = floorf(iy);
    int x0 = (int)fx, y0 = (int)fy;
    float wx1 = ix - fx, wy1 = iy - fy;
    float wx0 = 1.f - wx1, wy0 = 1.f - wy1;
    int base = FO4[lvl] + n * (H * W * c4);
    bool vx0 = (unsigned)x0 < (unsigned)W;
    bool vx1 = (unsigned)(x0 + 1) < (unsigned)W;
    bool vy0 = (unsigned)y0 < (unsigned)H;
    bool vy1 = (unsigned)(y0 + 1) < (unsigned)H;
    int r0 = y0 * W, r1 = r0 + W;
    if (vy0 && vx0) { o00 = base + (r0 + x0) * c4;     w00 = wy0 * wx0; }
    if (vy0 && vx1) { o01 = base + (r0 + x0 + 1) * c4; w01 = wy0 * wx1; }
    if (vy1 && vx0) { o10 = base + (r1 + x0) * c4;     w10 = wy1 * wx0; }
    if (vy1 && vx1) { o11 = base + (r1 + x0 + 1) * c4; w11 = wy1 * wx1; }
}

// ---------------- main: pipelined gather + GEMM + blend ----------------
// smem: double-buffered [CHUNK rows][64 pts] with stride 66.
// Per iter: issue corner LDGs for chunk i+1; GEMM chunk i; combine+STS chunk i+1.
__global__ void __launch_bounds__(256) main_kernel(
    const float* __restrict__ sp, const float* __restrict__ query,
    const float* __restrict__ be0, const float* __restrict__ be1,
    const float* __restrict__ be2, const float* __restrict__ be3,
    float* __restrict__ outq) {
    __shared__ float gsm[2][CHUNK * GSTRIDE];

    int t = threadIdx.x;
    int qb = blockIdx.x * PTS_PER_BLK;
    int pt = t >> 2, ci = t & 3;
    int q = qb + pt;
    int lane = t & 31, w = t >> 5;
    int pbase = w * 8;

    bool valid = q < NPTS;
    float gx = 0.f, gy = 0.f;
    int n = 0;
    if (valid) {
        gx = __ldg(&sp[2 * q]);
        gy = __ldg(&sp[2 * q + 1]);
        n = q / 4131;  // 27*153
    }

    unsigned long long acc[4][4];
#pragma unroll
    for (int k = 0; k < 4; k++)
#pragma unroll
        for (int pr = 0; pr < 4; pr++) acc[k][pr] = 0ull;

    float w00, w01, w10, w11;
    int o00, o01, o10, o11, lf;
    const float4* f4 = (const float4*)d_fT;
    const float4* w4 = (const float4*)d_weT;
    const float2* gs2_0 = (const float2*)gsm[0];
    const float2* gs2_1 = (const float2*)gsm[1];

    // ---- prologue: gather chunk 0 into buf0 ----
    setgeom(valid, gx, gy, n, 0, lf, w00, w01, w10, w11, o00, o01, o10, o11);
    {
        int c4loc = ci;  // chunk0: level c4 index = ci
        float4 a = f4[o00 + c4loc], b = f4[o01 + c4loc];
        float4 c = f4[o10 + c4loc], d = f4[o11 + c4loc];
        float g0 = w00 * a.x + w01 * b.x + w10 * c.x + w11 * d.x;
        float g1 = w00 * a.y + w01 * b.y + w10 * c.y + w11 * d.y;
        float g2 = w00 * a.z + w01 * b.z + w10 * c.z + w11 * d.z;
        float g3 = w00 * a.w + w01 * b.w + w10 * c.w + w11 * d.w;
        int lc = 4 * ci;
        gsm[0][(lc + 0) * GSTRIDE + pt] = g0;
        gsm[0][(lc + 1) * GSTRIDE + pt] = g1;
        gsm[0][(lc + 2) * GSTRIDE + pt] = g2;
        gsm[0][(lc + 3) * GSTRIDE + pt] = g3;
    }
    __syncthreads();

#pragma unroll 1
    for (int i = 0; i < NCHUNK; i++) {
        int cur = i & 1;
        float4 ra, rb, rc, rd;
        bool more = (i < NCHUNK - 1);
        if (more) {
            int ip = i + 1;
            if (ip == 3)  setgeom(valid, gx, gy, n, 1, lf, w00, w01, w10, w11, o00, o01, o10, o11);
            if (ip == 9)  setgeom(valid, gx, gy, n, 2, lf, w00, w01, w10, w11, o00, o01, o10, o11);
            if (ip == 21) setgeom(valid, gx, gy, n, 3, lf, w00, w01, w10, w11, o00, o01, o10, o11);
            int c4loc = (ip - lf) * 4 + ci;
            ra = f4[o00 + c4loc];
            rb = f4[o01 + c4loc];
            rc = f4[o10 + c4loc];
            rd = f4[o11 + c4loc];
        }

        // ---- GEMM chunk i: 16 channels ----
        const float2* gs2 = cur ? gs2_1 : gs2_0;
#pragma unroll
        for (int c4l = 0; c4l < 4; c4l++) {
            int gc4 = i * 4 + c4l;   // global c4 index 0..179
#pragma unroll
            for (int j = 0; j < 4; j++) {
                float4 wj = w4[(gc4 * 4 + j) * 32 + lane];
                unsigned long long wp0 = bcast2(wj.x);
                unsigned long long wp1 = bcast2(wj.y);
                unsigned long long wp2 = bcast2(wj.z);
                unsigned long long wp3 = bcast2(wj.w);
                int gbase2 = ((4 * c4l + j) * GSTRIDE + pbase) >> 1;
#pragma unroll
                for (int pr = 0; pr < 4; pr++) {
                    float2 gf = gs2[gbase2 + pr];
                    unsigned long long g;
                    memcpy(&g, &gf, 8);
                    fma2(acc[0][pr], g, wp0);
                    fma2(acc[1][pr], g, wp1);
                    fma2(acc[2][pr], g, wp2);
                    fma2(acc[3][pr], g, wp3);
                }
            }
        }

        if (more) {
            float* buf = gsm[cur ^ 1];
            float g0 = w00 * ra.x + w01 * rb.x + w10 * rc.x + w11 * rd.x;
            float g1 = w00 * ra.y + w01 * rb.y + w10 * rc.y + w11 * rd.y;
            float g2 = w00 * ra.z + w01 * rb.z + w10 * rc.z + w11 * rd.z;
            float g3 = w00 * ra.w + w01 * rb.w + w10 * rc.w + w11 * rd.w;
            int lc = 4 * ci;
            buf[(lc + 0) * GSTRIDE + pt] = g0;
            buf[(lc + 1) * GSTRIDE + pt] = g1;
            buf[(lc + 2) * GSTRIDE + pt] = g2;
            buf[(lc + 3) * GSTRIDE + pt] = g3;
        }
        __syncthreads();
    }

    // ---- epilogue: blend + store ----
    const float4* b04 = (const float4*)be0;
    const float4* b14 = (const float4*)be1;
    const float4* b24 = (const float4*)be2;
    const float4* b34 = (const float4*)be3;
    float4 v0 = b04[lane], v1 = b14[lane], v2 = b24[lane], v3 = b34[lane];
    float4 bs;
    bs.x = 0.025f * (v0.x + v1.x + v2.x + v3.x);
    bs.y = 0.025f * (v0.y + v1.y + v2.y + v3.y);
    bs.z = 0.025f * (v0.z + v1.z + v2.z + v3.z);
    bs.w = 0.025f * (v0.w + v1.w + v2.w + v3.w);

    const float4* q4 = (const float4*)query;
    float4* oq4 = (float4*)outq;
#pragma unroll
    for (int pr = 0; pr < 4; pr++) {
#pragma unroll
        for (int h = 0; h < 2; h++) {
            int qq = qb + w * 8 + 2 * pr + h;
            if (qq < NPTS) {
                float a0 = h ? hi2(acc[0][pr]) : lo2(acc[0][pr]);
                float a1 = h ? hi2(acc[1][pr]) : lo2(acc[1][pr]);
                float a2 = h ? hi2(acc[2][pr]) : lo2(acc[2][pr]);
                float a3 = h ? hi2(acc[3][pr]) : lo2(acc[3][pr]);
                float4 qv = q4[(size_t)qq * 32 + lane];
                float4 r;
                r.x = 0.025f * a0 + bs.x + 0.9f * qv.x;
                r.y = 0.025f * a1 + bs.y + 0.9f * qv.y;
                r.z = 0.025f * a2 + bs.z + 0.9f * qv.z;
                r.w = 0.025f * a3 + bs.w + 0.9f * qv.w;
                oq4[(size_t)qq * 32 + lane] = r;
            }
        }
    }
}

// ---------------- final conv: [b,t1] x (1152 -> 128) per p ----------------
__global__ void __launch_bounds__(256) conv_kernel(const float* __restrict__ nq,
                                                   const float* __restrict__ conv_b,
                                                   float* __restrict__ nv) {
    extern __shared__ float xs[];
    int bi = blockIdx.x;  // 0..485
    int t = threadIdx.x;
    const float4* src = (const float4*)(nq + (size_t)bi * PK * CC);
    float4* xs4 = (float4*)xs;
    for (int i = t; i < PK * 32; i += 256) xs4[i] = src[i];
    __syncthreads();

    int o = t & 127;
    int half = t >> 7;
    int p0 = half * 9;
    float acc[9];
#pragma unroll
    for (int j = 0; j < 9; j++) acc[j] = 0.f;

    int pbase[9];
#pragma unroll
    for (int j = 0; j < 9; j++) {
        int p = p0 + j;
        pbase[j] = (p < PP) ? p * 288 : 0;   // clamp, never stored
    }

    for (int i4 = 0; i4 < 288; i4++) {
        int i = i4 * 4;
        float w0 = d_cwT[(i + 0) * 128 + o];
        float w1 = d_cwT[(i + 1) * 128 + o];
        float w2 = d_cwT[(i + 2) * 128 + o];
        float w3 = d_cwT[(i + 3) * 128 + o];
#pragma unroll
        for (int j = 0; j < 9; j++) {
            float4 x = xs4[pbase[j] + i4];
            acc[j] = fmaf(x.x, w0, acc[j]);
            acc[j] = fmaf(x.y, w1, acc[j]);
            acc[j] = fmaf(x.z, w2, acc[j]);
            acc[j] = fmaf(x.w, w3, acc[j]);
        }
    }
    float cb = conv_b[o];
#pragma unroll
    for (int j = 0; j < 9; j++) {
        int p = p0 + j;
        if (p < PP) nv[((size_t)bi * PP + p) * 128 + o] = acc[j] + cb;
    }
}

// ---------------- launch ----------------
extern "C" void kernel_launch(void* const* d_in, const int* in_sizes, int n_in,
                              void* d_out, int out_size) {
    const float* f0     = (const float*)d_in[0];
    const float* f1     = (const float*)d_in[1];
    const float* f2     = (const float*)d_in[2];
    const float* f3     = (const float*)d_in[3];
    const float* query  = (const float*)d_in[4];
    const float* key    = (const float*)d_in[5];
    const float* value  = (const float*)d_in[6];
    const float* w_off  = (const float*)d_in[7];
    const float* b_off  = (const float*)d_in[8];
    const float* w_attn = (const float*)d_in[9];
    const float* b_attn = (const float*)d_in[10];
    const float* we0    = (const float*)d_in[11];
    const float* be0    = (const float*)d_in[12];
    const float* we1    = (const float*)d_in[13];
    const float* be1    = (const float*)d_in[14];
    const float* we2    = (const float*)d_in[15];
    const float* be2    = (const float*)d_in[16];
    const float* we3    = (const float*)d_in[17];
    const float* be3    = (const float*)d_in[18];
    const float* conv_w = (const float*)d_in[19];
    const float* conv_b = (const float*)d_in[20];

    float* out   = (float*)d_out;
    float* outQ  = out + OUT_Q_OFF;
    float* outV  = out + OUT_V_OFF;
    float* outSP = out + OUT_SP_OFF;

    dim3 tb(32, 8);
    tposef_kernel<<<dim3(3, 2, 18 * 96), tb>>>(f0, 48, 96, 72, FT_OFF0);
    tposef_kernel<<<dim3(2, 3, 18 * 48), tb>>>(f1, 96, 48, 36, FT_OFF1);
    tposef_kernel<<<dim3(1, 6, 18 * 24), tb>>>(f2, 192, 24, 18, FT_OFF2);
    tposef_kernel<<<dim3(1, 12, 18 * 12), tb>>>(f3, 384, 12, 9, FT_OFF3);

    wtrans_kernel<<<(48 * 128 + 255) / 256, 256>>>(we0, 48, 0);
    wtrans_kernel<<<(96 * 128 + 255) / 256, 256>>>(we1, 96, 6144);
    wtrans_kernel<<<(192 * 128 + 255) / 256, 256>>>(we2, 192, 18432);
    wtrans_kernel<<<(384 * 128 + 255) / 256, 256>>>(we3, 384, 43008);
    cwtrans_kernel<<<576, 256>>>(conv_w);

    pos_kernel<<<9295, 256>>>(query, key, value, w_off, b_off, w_attn, b_attn, outSP);

    main_kernel<<<(NPTS + PTS_PER_BLK - 1) / PTS_PER_BLK, 256>>>(
        outSP, query, be0, be1, be2, be3, outQ);

    cudaFuncSetAttribute(conv_kernel, cudaFuncAttributeMaxDynamicSharedMemorySize, 78336);
    conv_kernel<<<486, 256, 78336>>>(outQ, conv_b, outV);
}

// round 9
// speedup vs baseline: 2.2066x; 1.5870x over previous
#include <cuda_runtime.h>
#include <cuda_bf16.h>
#include <math.h>
#include <stdint.h>

// ---------------- problem constants ----------------
#define NPTS   74358      // 2 * 243 * 153
#define PK     153
#define PP     17
#define CC     128

// feature levels: C_l = {48,96,192,384}, H = {96,48,24,12}, W = {72,36,18,9}
#define FT_OFF0 0
#define FT_OFF1 5971968
#define FT_OFF2 8957952
#define FT_OFF3 10450944
#define FT_TOTAL 11197440

// output regions (floats)
#define OUT_Q_OFF  0
#define OUT_V_OFF  9517824
#define OUT_SP_OFF 10575360

#define NCH     45          // K chunks of 16 (720 total, no pad)
#define ASTRIDE 48          // bytes per point-row in A smem (24 bf16)

// ---------------- device scratch ----------------
__device__ __nv_bfloat16 d_fTb[FT_TOTAL];                  // bf16 NHWC feature maps
__device__ __align__(16) uint32_t d_wBf[45 * 8 * 32 * 4];  // B in mma-fragment layout
__device__ float d_bsum[128];                              // 0.025 * sum(be_l)
__device__ float d_cwT[1152 * 128];

// ---------------- helpers ----------------
__device__ __forceinline__ uint32_t smem_to_u32(const void* p) {
    uint32_t a;
    asm("{ .reg .u64 t; cvta.to.shared.u64 t, %1; cvt.u32.u64 %0, t; }" : "=r"(a) : "l"(p));
    return a;
}
__device__ __forceinline__ void ldsm_x4(uint32_t* a, uint32_t saddr) {
    asm volatile("ldmatrix.sync.aligned.m8n8.x4.shared.b16 {%0,%1,%2,%3}, [%4];"
                 : "=r"(a[0]), "=r"(a[1]), "=r"(a[2]), "=r"(a[3]) : "r"(saddr));
}
__device__ __forceinline__ void mma16816(float* d, const uint32_t* a, uint32_t b0, uint32_t b1) {
    asm volatile(
        "mma.sync.aligned.m16n8k16.row.col.f32.bf16.bf16.f32 "
        "{%0,%1,%2,%3}, {%4,%5,%6,%7}, {%8,%9}, {%0,%1,%2,%3};"
        : "+f"(d[0]), "+f"(d[1]), "+f"(d[2]), "+f"(d[3])
        : "r"(a[0]), "r"(a[1]), "r"(a[2]), "r"(a[3]), "r"(b0), "r"(b1));
}
#define FMA_BF16X2(r, a, b, c) \
    asm("fma.rn.bf16x2 %0, %1, %2, %3;" : "=r"(r) : "r"(a), "r"(b), "r"(c))
#define CVT_BF16X2_BCAST(r, f) \
    asm("cvt.rn.bf16x2.f32 %0, %1, %2;" : "=r"(r) : "f"(f), "f"(f))

// ---------------- prep: feature transpose NCHW fp32 -> NHWC bf16 ----------------
__global__ void tposef_kernel(const float* __restrict__ in, int C, int H, int W, int outOff) {
    __shared__ float tile[32][33];
    int nz = blockIdx.z;
    int n = nz / H, y = nz % H;
    int x0 = blockIdx.x * 32, c0 = blockIdx.y * 32;
    int tx = threadIdx.x, ty = threadIdx.y;
#pragma unroll
    for (int k = 0; k < 4; k++) {
        int c = c0 + ty + 8 * k, x = x0 + tx;
        if (c < C && x < W)
            tile[ty + 8 * k][tx] = in[((size_t)(n * C + c) * H + y) * W + x];
    }
    __syncthreads();
#pragma unroll
    for (int k = 0; k < 4; k++) {
        int x = x0 + ty + 8 * k, c = c0 + tx;
        if (c < C && x < W)
            d_fTb[outOff + ((size_t)(n * H + y) * W + x) * C + c] =
                __float2bfloat16(tile[tx][ty + 8 * k]);
    }
}

// ---------------- prep: B in mma fragment layout ----------------
// flat u32 index e = ((c*8 + np)*32 + lane)*4 + q ; q = t*2 + reg
// ntile = np*2 + t ; n = ntile*8 + lane/4 ; k = c*16 + reg*8 + 2*(lane%4) + h
__global__ void wbfprep_kernel(const float* __restrict__ we0, const float* __restrict__ we1,
                               const float* __restrict__ we2, const float* __restrict__ we3) {
    int e = blockIdx.x * 256 + threadIdx.x;
    if (e >= 45 * 8 * 32 * 4) return;
    int q = e & 3, lane = (e >> 2) & 31, np = (e >> 7) & 7, c = e >> 10;
    int t = q >> 1, reg = q & 1;
    int n = (np * 2 + t) * 8 + (lane >> 2);
    int k = c * 16 + reg * 8 + 2 * (lane & 3);
    uint32_t out = 0;
#pragma unroll
    for (int h = 0; h < 2; h++) {
        int ch = k + h;  // always < 720
        float v;
        if (ch < 48)       v = we0[n * 48 + ch];
        else if (ch < 144) v = we1[n * 96 + (ch - 48)];
        else if (ch < 336) v = we2[n * 192 + (ch - 144)];
        else               v = we3[n * 384 + (ch - 336)];
        __nv_bfloat16 b = __float2bfloat16(v);
        out |= (uint32_t)__bfloat16_as_ushort(b) << (16 * h);
    }
    d_wBf[e] = out;
}

__global__ void bsum_kernel(const float* __restrict__ be0, const float* __restrict__ be1,
                            const float* __restrict__ be2, const float* __restrict__ be3) {
    int o = threadIdx.x;
    d_bsum[o] = 0.025f * (be0[o] + be1[o] + be2[o] + be3[o]);
}

__global__ void cwtrans_kernel(const float* __restrict__ cw) {
    int e = blockIdx.x * 256 + threadIdx.x;
    if (e < 1152 * 128) {
        int i = e >> 7, o = e & 127;
        int c = i & 127, k = i >> 7;
        d_cwT[e] = cw[(o * 128 + c) * 9 + k];
    }
}

// ---------------- sampling positions ----------------
__device__ __forceinline__ float dot4(float4 a, float4 b) {
    return a.x * b.x + a.y * b.y + a.z * b.z + a.w * b.w;
}

__global__ void pos_kernel(const float* __restrict__ query, const float* __restrict__ key,
                           const float* __restrict__ value,
                           const float* __restrict__ w_off, const float* __restrict__ b_off,
                           const float* __restrict__ w_attn, const float* __restrict__ b_attn,
                           float* __restrict__ spo) {
    int w = blockIdx.x * 8 + (threadIdx.x >> 5);
    if (w >= NPTS) return;
    int lane = threadIdx.x & 31;

    const float4* q4 = (const float4*)query;
    const float4* wo4 = (const float4*)w_off;
    float4 qv = q4[(size_t)w * 32 + lane];
    float d0 = dot4(qv, wo4[lane]);
    float d1 = dot4(qv, wo4[32 + lane]);

    int bt1 = w / PK;
    int p = (w % PK) % PP;
    const float4* v4 = (const float4*)value;
    const float4* wa4 = (const float4*)w_attn;
    float4 vv = v4[((size_t)bt1 * PP + p) * 32 + lane];
    float e0 = dot4(vv, wa4[lane]);
    float e1 = dot4(vv, wa4[32 + lane]);

#pragma unroll
    for (int s = 16; s; s >>= 1) {
        d0 += __shfl_xor_sync(0xFFFFFFFFu, d0, s);
        d1 += __shfl_xor_sync(0xFFFFFFFFu, d1, s);
        e0 += __shfl_xor_sync(0xFFFFFFFFu, e0, s);
        e1 += __shfl_xor_sync(0xFFFFFFFFu, e1, s);
    }
    if (lane == 0) {
        float o0 = tanhf(d0 + b_off[0]);
        float o1 = tanhf(d1 + b_off[1]);
        float l0 = e0 + b_attn[0], l1 = e1 + b_attn[1];
        float m = fmaxf(l0, l1);
        float x0 = expf(l0 - m), x1 = expf(l1 - m);
        float inv = 1.0f / (x0 + x1);
        spo[2 * w]     = key[2 * w]     + o0 * (x0 * inv);
        spo[2 * w + 1] = key[2 * w + 1] + o1 * (x1 * inv);
    }
}

// ---------------- bilinear geometry (element offsets into bf16 NHWC) ----------------
__device__ __forceinline__ void geomcalc(bool valid, float gx, float gy, int n, int lvl,
                                         int4& o, float4& wv) {
    const int Hs[4] = {96, 48, 24, 12};
    const int Ws[4] = {72, 36, 18, 9};
    const int Cs[4] = {48, 96, 192, 384};
    const int FO[4] = {FT_OFF0, FT_OFF1, FT_OFF2, FT_OFF3};
    o = make_int4(0, 0, 0, 0);
    wv = make_float4(0.f, 0.f, 0.f, 0.f);
    if (!valid) return;
    int H = Hs[lvl], W = Ws[lvl], C = Cs[lvl];
    float ix = ((gx + 1.f) * (float)W - 1.f) * 0.5f;
    float iy = ((gy + 1.f) * (float)H - 1.f) * 0.5f;
    float fx = floorf(ix), fy = floorf(iy);
    int x0 = (int)fx, y0 = (int)fy;
    float wx1 = ix - fx, wy1 = iy - fy;
    float wx0 = 1.f - wx1, wy0 = 1.f - wy1;
    int base = FO[lvl] + n * (H * W * C);
    bool vx0 = (unsigned)x0 < (unsigned)W;
    bool vx1 = (unsigned)(x0 + 1) < (unsigned)W;
    bool vy0 = (unsigned)y0 < (unsigned)H;
    bool vy1 = (unsigned)(y0 + 1) < (unsigned)H;
    int r0 = y0 * W, r1 = r0 + W;
    if (vy0 && vx0) { o.x = base + (r0 + x0) * C;     wv.x = wy0 * wx0; }
    if (vy0 && vx1) { o.y = base + (r0 + x0 + 1) * C; wv.y = wy0 * wx1; }
    if (vy1 && vx0) { o.z = base + (r1 + x0) * C;     wv.z = wy1 * wx0; }
    if (vy1 && vx1) { o.w = base + (r1 + x0 + 1) * C; wv.w = wy1 * wx1; }
}

// ---------------- gather helpers (2 tasks per thread, chunk = 16 channels = 4 c4) ----------------
__device__ __forceinline__ void gather_load(int cn, int tid, const int4* goff,
                                            const uint2* fp2, uint2 ca[2][4], int cidx[2]) {
#pragma unroll
    for (int s = 0; s < 2; s++) {
        int task = s * 256 + tid;
        int c4i = task & 3, pt = task >> 2;
        int gc4 = cn * 4 + c4i;
        int lvl = (gc4 < 12) ? 0 : (gc4 < 36) ? 1 : (gc4 < 84) ? 2 : 3;
        int gb  = (gc4 < 12) ? 0 : (gc4 < 36) ? 12 : (gc4 < 84) ? 36 : 84;
        int chl = (gc4 - gb) * 4;
        int idx = lvl * 128 + pt;
        cidx[s] = idx;
        int4 o = goff[idx];
        ca[s][0] = fp2[(o.x + chl) >> 2];
        ca[s][1] = fp2[(o.y + chl) >> 2];
        ca[s][2] = fp2[(o.z + chl) >> 2];
        ca[s][3] = fp2[(o.w + chl) >> 2];
    }
}

__device__ __forceinline__ void gather_store(int tid, const float4* gwv,
                                             uint2 ca[2][4], const int cidx[2],
                                             unsigned char* abuf) {
#pragma unroll
    for (int s = 0; s < 2; s++) {
        int task = s * 256 + tid;
        int c4i = task & 3, pt = task >> 2;
        float4 wv = gwv[cidx[s]];
        uint32_t w00, w01, w10, w11;
        CVT_BF16X2_BCAST(w00, wv.x);
        CVT_BF16X2_BCAST(w01, wv.y);
        CVT_BF16X2_BCAST(w10, wv.z);
        CVT_BF16X2_BCAST(w11, wv.w);
        uint32_t gx0 = 0, gy0 = 0;
        FMA_BF16X2(gx0, ca[s][0].x, w00, gx0);
        FMA_BF16X2(gx0, ca[s][1].x, w01, gx0);
        FMA_BF16X2(gx0, ca[s][2].x, w10, gx0);
        FMA_BF16X2(gx0, ca[s][3].x, w11, gx0);
        FMA_BF16X2(gy0, ca[s][0].y, w00, gy0);
        FMA_BF16X2(gy0, ca[s][1].y, w01, gy0);
        FMA_BF16X2(gy0, ca[s][2].y, w10, gy0);
        FMA_BF16X2(gy0, ca[s][3].y, w11, gy0);
        uint2 g = make_uint2(gx0, gy0);
        *(uint2*)(abuf + pt * ASTRIDE + c4i * 8) = g;
    }
}

// ---------------- main: mma.sync bf16 GEMM with gathered A ----------------
// block: 128 pts x 128 outs; 8 warps: warp_m = wid&3 (M32), warp_n = wid>>2 (N64)
__global__ void __launch_bounds__(256) main3_kernel(
    const float* __restrict__ sp, const float* __restrict__ query,
    float* __restrict__ outq) {
    __shared__ __align__(16) unsigned char abuf[2][128 * ASTRIDE];
    __shared__ int4 goff[512];
    __shared__ float4 gwv[512];

    int tid = threadIdx.x;
    int lane = tid & 31, wid = tid >> 5;
    int warp_m = wid & 3, warp_n = wid >> 2;
    int qb = blockIdx.x * 128;

    // ---- geometry ----
#pragma unroll
    for (int s = 0; s < 2; s++) {
        int task = s * 256 + tid;
        int lvl = task >> 7, pt = task & 127;
        int q = qb + pt;
        bool valid = q < NPTS;
        float gx = 0.f, gy = 0.f;
        int n = 0;
        if (valid) {
            gx = sp[2 * q];
            gy = sp[2 * q + 1];
            n = q / 4131;   // 27*153
        }
        int4 o; float4 wv;
        geomcalc(valid, gx, gy, n, lvl, o, wv);
        goff[task] = o;
        gwv[task] = wv;
    }
    __syncthreads();

    float d[2][8][4];
#pragma unroll
    for (int i = 0; i < 2; i++)
#pragma unroll
        for (int j = 0; j < 8; j++)
#pragma unroll
            for (int k = 0; k < 4; k++) d[i][j][k] = 0.f;

    const uint2* fp2 = (const uint2*)d_fTb;
    const uint4* wB4 = (const uint4*)d_wBf;
    uint32_t abase = smem_to_u32(abuf);

    uint2 ca[2][4];
    int cidx[2];
    uint4 bcur[4], bnext[4];

    // ---- prologue: chunk 0 ----
    gather_load(0, tid, goff, fp2, ca, cidx);
#pragma unroll
    for (int i = 0; i < 4; i++)
        bcur[i] = wB4[(0 * 8 + warp_n * 4 + i) * 32 + lane];
    gather_store(tid, gwv, ca, cidx, abuf[0]);
    __syncthreads();

#pragma unroll 1
    for (int c = 0; c < NCH; c++) {
        bool more = (c + 1) < NCH;
        if (more) {
            gather_load(c + 1, tid, goff, fp2, ca, cidx);
#pragma unroll
            for (int i = 0; i < 4; i++)
                bnext[i] = wB4[((c + 1) * 8 + warp_n * 4 + i) * 32 + lane];
        }

        // ---- ldmatrix + mma on chunk c ----
        uint32_t a[2][4];
        uint32_t ab = abase + (c & 1) * (128 * ASTRIDE) +
                      (warp_m * 32 + (lane & 15)) * ASTRIDE + (lane >> 4) * 16;
        ldsm_x4(a[0], ab);
        ldsm_x4(a[1], ab + 16 * ASTRIDE);
#pragma unroll
        for (int nt = 0; nt < 8; nt++) {
            uint32_t b0 = (nt & 1) ? bcur[nt >> 1].z : bcur[nt >> 1].x;
            uint32_t b1 = (nt & 1) ? bcur[nt >> 1].w : bcur[nt >> 1].y;
            mma16816(d[0][nt], a[0], b0, b1);
            mma16816(d[1][nt], a[1], b0, b1);
        }

        if (more) {
            gather_store(tid, gwv, ca, cidx, abuf[(c + 1) & 1]);
#pragma unroll
            for (int i = 0; i < 4; i++) bcur[i] = bnext[i];
        }
        __syncthreads();
    }

    // ---- epilogue: blend + store ----
#pragma unroll
    for (int mt = 0; mt < 2; mt++) {
#pragma unroll
        for (int rr = 0; rr < 2; rr++) {
            int q = qb + warp_m * 32 + mt * 16 + rr * 8 + (lane >> 2);
            if (q < NPTS) {
#pragma unroll
                for (int nt = 0; nt < 8; nt++) {
                    int o = warp_n * 64 + nt * 8 + 2 * (lane & 3);
                    float2 qv = *(const float2*)&query[(size_t)q * 128 + o];
                    float2 bsv = *(const float2*)&d_bsum[o];
                    float2 r;
                    r.x = 0.025f * d[mt][nt][rr * 2 + 0] + bsv.x + 0.9f * qv.x;
                    r.y = 0.025f * d[mt][nt][rr * 2 + 1] + bsv.y + 0.9f * qv.y;
                    *(float2*)&outq[(size_t)q * 128 + o] = r;
                }
            }
        }
    }
}

// ---------------- final conv: [b,t1] x (1152 -> 128) per p ----------------
__global__ void __launch_bounds__(256) conv_kernel(const float* __restrict__ nq,
                                                   const float* __restrict__ conv_b,
                                                   float* __restrict__ nv) {
    extern __shared__ float xs[];
    int bi = blockIdx.x;  // 0..485
    int t = threadIdx.x;
    const float4* src = (const float4*)(nq + (size_t)bi * PK * CC);
    float4* xs4 = (float4*)xs;
    for (int i = t; i < PK * 32; i += 256) xs4[i] = src[i];
    __syncthreads();

    int o = t & 127;
    int half = t >> 7;
    int p0 = half * 9;
    float acc[9];
#pragma unroll
    for (int j = 0; j < 9; j++) acc[j] = 0.f;

    int pbase[9];
#pragma unroll
    for (int j = 0; j < 9; j++) {
        int p = p0 + j;
        pbase[j] = (p < PP) ? p * 288 : 0;   // clamp, never stored
    }

    for (int i4 = 0; i4 < 288; i4++) {
        int i = i4 * 4;
        float w0 = d_cwT[(i + 0) * 128 + o];
        float w1 = d_cwT[(i + 1) * 128 + o];
        float w2 = d_cwT[(i + 2) * 128 + o];
        float w3 = d_cwT[(i + 3) * 128 + o];
#pragma unroll
        for (int j = 0; j < 9; j++) {
            float4 x = xs4[pbase[j] + i4];
            acc[j] = fmaf(x.x, w0, acc[j]);
            acc[j] = fmaf(x.y, w1, acc[j]);
            acc[j] = fmaf(x.z, w2, acc[j]);
            acc[j] = fmaf(x.w, w3, acc[j]);
        }
    }
    float cb = conv_b[o];
#pragma unroll
    for (int j = 0; j < 9; j++) {
        int p = p0 + j;
        if (p < PP) nv[((size_t)bi * PP + p) * 128 + o] = acc[j] + cb;
    }
}

// ---------------- launch ----------------
extern "C" void kernel_launch(void* const* d_in, const int* in_sizes, int n_in,
                              void* d_out, int out_size) {
    const float* f0     = (const float*)d_in[0];
    const float* f1     = (const float*)d_in[1];
    const float* f2     = (const float*)d_in[2];
    const float* f3     = (const float*)d_in[3];
    const float* query  = (const float*)d_in[4];
    const float* key    = (const float*)d_in[5];
    const float* value  = (const float*)d_in[6];
    const float* w_off  = (const float*)d_in[7];
    const float* b_off  = (const float*)d_in[8];
    const float* w_attn = (const float*)d_in[9];
    const float* b_attn = (const float*)d_in[10];
    const float* we0    = (const float*)d_in[11];
    const float* be0    = (const float*)d_in[12];
    const float* we1    = (const float*)d_in[13];
    const float* be1    = (const float*)d_in[14];
    const float* we2    = (const float*)d_in[15];
    const float* be2    = (const float*)d_in[16];
    const float* we3    = (const float*)d_in[17];
    const float* be3    = (const float*)d_in[18];
    const float* conv_w = (const float*)d_in[19];
    const float* conv_b = (const float*)d_in[20];

    float* out   = (float*)d_out;
    float* outQ  = out + OUT_Q_OFF;
    float* outV  = out + OUT_V_OFF;
    float* outSP = out + OUT_SP_OFF;

    dim3 tb(32, 8);
    tposef_kernel<<<dim3(3, 2, 18 * 96), tb>>>(f0, 48, 96, 72, FT_OFF0);
    tposef_kernel<<<dim3(2, 3, 18 * 48), tb>>>(f1, 96, 48, 36, FT_OFF1);
    tposef_kernel<<<dim3(1, 6, 18 * 24), tb>>>(f2, 192, 24, 18, FT_OFF2);
    tposef_kernel<<<dim3(1, 12, 18 * 12), tb>>>(f3, 384, 12, 9, FT_OFF3);

    wbfprep_kernel<<<180, 256>>>(we0, we1, we2, we3);
    bsum_kernel<<<1, 128>>>(be0, be1, be2, be3);
    cwtrans_kernel<<<576, 256>>>(conv_w);

    pos_kernel<<<9295, 256>>>(query, key, value, w_off, b_off, w_attn, b_attn, outSP);

    main3_kernel<<<(NPTS + 127) / 128, 256>>>(outSP, query, outQ);

    cudaFuncSetAttribute(conv_kernel, cudaFuncAttributeMaxDynamicSharedMemorySize, 78336);
    conv_kernel<<<486, 256, 78336>>>(outQ, conv_b, outV);
}

// round 10
// speedup vs baseline: 3.4072x; 1.5441x over previous
#include <cuda_runtime.h>
#include <cuda_bf16.h>
#include <math.h>
#include <stdint.h>

// ---------------- problem constants ----------------
#define NPTS   74358      // 2 * 243 * 153
#define PK     153
#define PP     17
#define CC     128
#define MROWS  8262       // 486 * 17 rows of the conv GEMM (= 486*153*128 / 1152)

// feature levels: C_l = {48,96,192,384}, H = {96,48,24,12}, W = {72,36,18,9}
#define FT_OFF0 0
#define FT_OFF1 5971968
#define FT_OFF2 8957952
#define FT_OFF3 10450944
#define FT_TOTAL 11197440

// output regions (floats)
#define OUT_Q_OFF  0
#define OUT_V_OFF  9517824
#define OUT_SP_OFF 10575360

#define NCH     45          // K chunks of 16 (720 total, no pad)
#define ASTRIDE 48          // bytes per point-row in A smem (24 bf16)

// ---------------- device scratch ----------------
__device__ __nv_bfloat16 d_fTb[FT_TOTAL];                  // bf16 NHWC feature maps
__device__ __align__(16) uint32_t d_wBf[45 * 8 * 32 * 4];  // sampling B frags
__device__ float d_bsum[128];                              // 0.025 * sum(be_l)
__device__ __align__(16) uint32_t d_nqh[4758912];          // new_query hi bf16 pairs
__device__ __align__(16) uint32_t d_nql[4758912];          // new_query lo bf16 pairs
__device__ __align__(16) uint32_t d_cwh[72 * 8 * 32 * 4];  // conv W hi frags
__device__ __align__(16) uint32_t d_cwl[72 * 8 * 32 * 4];  // conv W lo frags

// ---------------- helpers ----------------
__device__ __forceinline__ uint32_t smem_to_u32(const void* p) {
    uint32_t a;
    asm("{ .reg .u64 t; cvta.to.shared.u64 t, %1; cvt.u32.u64 %0, t; }" : "=r"(a) : "l"(p));
    return a;
}
__device__ __forceinline__ void ldsm_x4(uint32_t* a, uint32_t saddr) {
    asm volatile("ldmatrix.sync.aligned.m8n8.x4.shared.b16 {%0,%1,%2,%3}, [%4];"
                 : "=r"(a[0]), "=r"(a[1]), "=r"(a[2]), "=r"(a[3]) : "r"(saddr));
}
__device__ __forceinline__ void mma16816(float* d, const uint32_t* a, uint32_t b0, uint32_t b1) {
    asm volatile(
        "mma.sync.aligned.m16n8k16.row.col.f32.bf16.bf16.f32 "
        "{%0,%1,%2,%3}, {%4,%5,%6,%7}, {%8,%9}, {%0,%1,%2,%3};"
        : "+f"(d[0]), "+f"(d[1]), "+f"(d[2]), "+f"(d[3])
        : "r"(a[0]), "r"(a[1]), "r"(a[2]), "r"(a[3]), "r"(b0), "r"(b1));
}
#define FMA_BF16X2(r, a, b, c) \
    asm("fma.rn.bf16x2 %0, %1, %2, %3;" : "=r"(r) : "r"(a), "r"(b), "r"(c))
#define CVT_BF16X2_BCAST(r, f) \
    asm("cvt.rn.bf16x2.f32 %0, %1, %2;" : "=r"(r) : "f"(f), "f"(f))

__device__ __forceinline__ uint32_t pack_hi(float x, float y) {
    __nv_bfloat16 hx = __float2bfloat16_rn(x);
    __nv_bfloat16 hy = __float2bfloat16_rn(y);
    return (uint32_t)__bfloat16_as_ushort(hx) | ((uint32_t)__bfloat16_as_ushort(hy) << 16);
}
__device__ __forceinline__ uint32_t pack_lo(float x, float y, uint32_t hi) {
    float hx = __bfloat162float(__ushort_as_bfloat16((unsigned short)(hi & 0xFFFF)));
    float hy = __bfloat162float(__ushort_as_bfloat16((unsigned short)(hi >> 16)));
    __nv_bfloat16 lx = __float2bfloat16_rn(x - hx);
    __nv_bfloat16 ly = __float2bfloat16_rn(y - hy);
    return (uint32_t)__bfloat16_as_ushort(lx) | ((uint32_t)__bfloat16_as_ushort(ly) << 16);
}

// ---------------- prep: feature transpose NCHW fp32 -> NHWC bf16 ----------------
__global__ void tposef_kernel(const float* __restrict__ in, int C, int H, int W, int outOff) {
    __shared__ float tile[32][33];
    int nz = blockIdx.z;
    int n = nz / H, y = nz % H;
    int x0 = blockIdx.x * 32, c0 = blockIdx.y * 32;
    int tx = threadIdx.x, ty = threadIdx.y;
#pragma unroll
    for (int k = 0; k < 4; k++) {
        int c = c0 + ty + 8 * k, x = x0 + tx;
        if (c < C && x < W)
            tile[ty + 8 * k][tx] = in[((size_t)(n * C + c) * H + y) * W + x];
    }
    __syncthreads();
#pragma unroll
    for (int k = 0; k < 4; k++) {
        int x = x0 + ty + 8 * k, c = c0 + tx;
        if (c < C && x < W)
            d_fTb[outOff + ((size_t)(n * H + y) * W + x) * C + c] =
                __float2bfloat16(tile[tx][ty + 8 * k]);
    }
}

// ---------------- prep: sampling B in mma fragment layout ----------------
__global__ void wbfprep_kernel(const float* __restrict__ we0, const float* __restrict__ we1,
                               const float* __restrict__ we2, const float* __restrict__ we3) {
    int e = blockIdx.x * 256 + threadIdx.x;
    if (e >= 45 * 8 * 32 * 4) return;
    int q = e & 3, lane = (e >> 2) & 31, np = (e >> 7) & 7, c = e >> 10;
    int t = q >> 1, reg = q & 1;
    int n = (np * 2 + t) * 8 + (lane >> 2);
    int k = c * 16 + reg * 8 + 2 * (lane & 3);
    uint32_t out = 0;
#pragma unroll
    for (int h = 0; h < 2; h++) {
        int ch = k + h;
        float v;
        if (ch < 48)       v = we0[n * 48 + ch];
        else if (ch < 144) v = we1[n * 96 + (ch - 48)];
        else if (ch < 336) v = we2[n * 192 + (ch - 144)];
        else               v = we3[n * 384 + (ch - 336)];
        __nv_bfloat16 b = __float2bfloat16(v);
        out |= (uint32_t)__bfloat16_as_ushort(b) << (16 * h);
    }
    d_wBf[e] = out;
}

// ---------------- prep: conv W hi/lo fragments ----------------
// A row layout: kf = k*128 + c ; W'[kf][o] = conv_w[o][c][k]
__global__ void wcfprep_kernel(const float* __restrict__ cw) {
    int e = blockIdx.x * 256 + threadIdx.x;
    if (e >= 72 * 8 * 32 * 4) return;
    int q = e & 3, lane = (e >> 2) & 31, np = (e >> 7) & 7, kc = e >> 10;
    int t = q >> 1, reg = q & 1;
    int n = (np * 2 + t) * 8 + (lane >> 2);
    int kf = kc * 16 + reg * 8 + 2 * (lane & 3);
    uint32_t oh = 0, ol = 0;
#pragma unroll
    for (int h = 0; h < 2; h++) {
        int kfe = kf + h;
        int k = kfe >> 7, c = kfe & 127;
        float v = cw[((size_t)n * 128 + c) * 9 + k];
        __nv_bfloat16 bh = __float2bfloat16_rn(v);
        float r = v - __bfloat162float(bh);
        __nv_bfloat16 bl = __float2bfloat16_rn(r);
        oh |= (uint32_t)__bfloat16_as_ushort(bh) << (16 * h);
        ol |= (uint32_t)__bfloat16_as_ushort(bl) << (16 * h);
    }
    d_cwh[e] = oh;
    d_cwl[e] = ol;
}

__global__ void bsum_kernel(const float* __restrict__ be0, const float* __restrict__ be1,
                            const float* __restrict__ be2, const float* __restrict__ be3) {
    int o = threadIdx.x;
    d_bsum[o] = 0.025f * (be0[o] + be1[o] + be2[o] + be3[o]);
}

// ---------------- sampling positions ----------------
__device__ __forceinline__ float dot4(float4 a, float4 b) {
    return a.x * b.x + a.y * b.y + a.z * b.z + a.w * b.w;
}

__global__ void pos_kernel(const float* __restrict__ query, const float* __restrict__ key,
                           const float* __restrict__ value,
                           const float* __restrict__ w_off, const float* __restrict__ b_off,
                           const float* __restrict__ w_attn, const float* __restrict__ b_attn,
                           float* __restrict__ spo) {
    int w = blockIdx.x * 8 + (threadIdx.x >> 5);
    if (w >= NPTS) return;
    int lane = threadIdx.x & 31;

    const float4* q4 = (const float4*)query;
    const float4* wo4 = (const float4*)w_off;
    float4 qv = q4[(size_t)w * 32 + lane];
    float d0 = dot4(qv, wo4[lane]);
    float d1 = dot4(qv, wo4[32 + lane]);

    int bt1 = w / PK;
    int p = (w % PK) % PP;
    const float4* v4 = (const float4*)value;
    const float4* wa4 = (const float4*)w_attn;
    float4 vv = v4[((size_t)bt1 * PP + p) * 32 + lane];
    float e0 = dot4(vv, wa4[lane]);
    float e1 = dot4(vv, wa4[32 + lane]);

#pragma unroll
    for (int s = 16; s; s >>= 1) {
        d0 += __shfl_xor_sync(0xFFFFFFFFu, d0, s);
        d1 += __shfl_xor_sync(0xFFFFFFFFu, d1, s);
        e0 += __shfl_xor_sync(0xFFFFFFFFu, e0, s);
        e1 += __shfl_xor_sync(0xFFFFFFFFu, e1, s);
    }
    if (lane == 0) {
        float o0 = tanhf(d0 + b_off[0]);
        float o1 = tanhf(d1 + b_off[1]);
        float l0 = e0 + b_attn[0], l1 = e1 + b_attn[1];
        float m = fmaxf(l0, l1);
        float x0 = expf(l0 - m), x1 = expf(l1 - m);
        float inv = 1.0f / (x0 + x1);
        spo[2 * w]     = key[2 * w]     + o0 * (x0 * inv);
        spo[2 * w + 1] = key[2 * w + 1] + o1 * (x1 * inv);
    }
}

// ---------------- bilinear geometry ----------------
__device__ __forceinline__ void geomcalc(bool valid, float gx, float gy, int n, int lvl,
                                         int4& o, float4& wv) {
    const int Hs[4] = {96, 48, 24, 12};
    const int Ws[4] = {72, 36, 18, 9};
    const int Cs[4] = {48, 96, 192, 384};
    const int FO[4] = {FT_OFF0, FT_OFF1, FT_OFF2, FT_OFF3};
    o = make_int4(0, 0, 0, 0);
    wv = make_float4(0.f, 0.f, 0.f, 0.f);
    if (!valid) return;
    int H = Hs[lvl], W = Ws[lvl], C = Cs[lvl];
    float ix = ((gx + 1.f) * (float)W - 1.f) * 0.5f;
    float iy = ((gy + 1.f) * (float)H - 1.f) * 0.5f;
    float fx = floorf(ix), fy = floorf(iy);
    int x0 = (int)fx, y0 = (int)fy;
    float wx1 = ix - fx, wy1 = iy - fy;
    float wx0 = 1.f - wx1, wy0 = 1.f - wy1;
    int base = FO[lvl] + n * (H * W * C);
    bool vx0 = (unsigned)x0 < (unsigned)W;
    bool vx1 = (unsigned)(x0 + 1) < (unsigned)W;
    bool vy0 = (unsigned)y0 < (unsigned)H;
    bool vy1 = (unsigned)(y0 + 1) < (unsigned)H;
    int r0 = y0 * W, r1 = r0 + W;
    if (vy0 && vx0) { o.x = base + (r0 + x0) * C;     wv.x = wy0 * wx0; }
    if (vy0 && vx1) { o.y = base + (r0 + x0 + 1) * C; wv.y = wy0 * wx1; }
    if (vy1 && vx0) { o.z = base + (r1 + x0) * C;     wv.z = wy1 * wx0; }
    if (vy1 && vx1) { o.w = base + (r1 + x0 + 1) * C; wv.w = wy1 * wx1; }
}

// ---------------- gather helpers ----------------
__device__ __forceinline__ void gather_load(int cn, int tid, const int4* goff,
                                            const uint2* fp2, uint2 ca[2][4], int cidx[2]) {
#pragma unroll
    for (int s = 0; s < 2; s++) {
        int task = s * 256 + tid;
        int c4i = task & 3, pt = task >> 2;
        int gc4 = cn * 4 + c4i;
        int lvl = (gc4 < 12) ? 0 : (gc4 < 36) ? 1 : (gc4 < 84) ? 2 : 3;
        int gb  = (gc4 < 12) ? 0 : (gc4 < 36) ? 12 : (gc4 < 84) ? 36 : 84;
        int chl = (gc4 - gb) * 4;
        int idx = lvl * 128 + pt;
        cidx[s] = idx;
        int4 o = goff[idx];
        ca[s][0] = fp2[(o.x + chl) >> 2];
        ca[s][1] = fp2[(o.y + chl) >> 2];
        ca[s][2] = fp2[(o.z + chl) >> 2];
        ca[s][3] = fp2[(o.w + chl) >> 2];
    }
}

__device__ __forceinline__ void gather_store(int tid, const float4* gwv,
                                             uint2 ca[2][4], const int cidx[2],
                                             unsigned char* abuf) {
#pragma unroll
    for (int s = 0; s < 2; s++) {
        int task = s * 256 + tid;
        int c4i = task & 3, pt = task >> 2;
        float4 wv = gwv[cidx[s]];
        uint32_t w00, w01, w10, w11;
        CVT_BF16X2_BCAST(w00, wv.x);
        CVT_BF16X2_BCAST(w01, wv.y);
        CVT_BF16X2_BCAST(w10, wv.z);
        CVT_BF16X2_BCAST(w11, wv.w);
        uint32_t gx0 = 0, gy0 = 0;
        FMA_BF16X2(gx0, ca[s][0].x, w00, gx0);
        FMA_BF16X2(gx0, ca[s][1].x, w01, gx0);
        FMA_BF16X2(gx0, ca[s][2].x, w10, gx0);
        FMA_BF16X2(gx0, ca[s][3].x, w11, gx0);
        FMA_BF16X2(gy0, ca[s][0].y, w00, gy0);
        FMA_BF16X2(gy0, ca[s][1].y, w01, gy0);
        FMA_BF16X2(gy0, ca[s][2].y, w10, gy0);
        FMA_BF16X2(gy0, ca[s][3].y, w11, gy0);
        uint2 g = make_uint2(gx0, gy0);
        *(uint2*)(abuf + pt * ASTRIDE + c4i * 8) = g;
    }
}

// ---------------- main: mma.sync bf16 GEMM with gathered A ----------------
__global__ void __launch_bounds__(256) main3_kernel(
    const float* __restrict__ sp, const float* __restrict__ query,
    float* __restrict__ outq) {
    __shared__ __align__(16) unsigned char abuf[2][128 * ASTRIDE];
    __shared__ int4 goff[512];
    __shared__ float4 gwv[512];

    int tid = threadIdx.x;
    int lane = tid & 31, wid = tid >> 5;
    int warp_m = wid & 3, warp_n = wid >> 2;
    int qb = blockIdx.x * 128;

#pragma unroll
    for (int s = 0; s < 2; s++) {
        int task = s * 256 + tid;
        int lvl = task >> 7, pt = task & 127;
        int q = qb + pt;
        bool valid = q < NPTS;
        float gx = 0.f, gy = 0.f;
        int n = 0;
        if (valid) {
            gx = sp[2 * q];
            gy = sp[2 * q + 1];
            n = q / 4131;
        }
        int4 o; float4 wv;
        geomcalc(valid, gx, gy, n, lvl, o, wv);
        goff[task] = o;
        gwv[task] = wv;
    }
    __syncthreads();

    float d[2][8][4];
#pragma unroll
    for (int i = 0; i < 2; i++)
#pragma unroll
        for (int j = 0; j < 8; j++)
#pragma unroll
            for (int k = 0; k < 4; k++) d[i][j][k] = 0.f;

    const uint2* fp2 = (const uint2*)d_fTb;
    const uint4* wB4 = (const uint4*)d_wBf;
    uint32_t abase = smem_to_u32(abuf);

    uint2 ca[2][4];
    int cidx[2];
    uint4 bcur[4], bnext[4];

    gather_load(0, tid, goff, fp2, ca, cidx);
#pragma unroll
    for (int i = 0; i < 4; i++)
        bcur[i] = wB4[(warp_n * 4 + i) * 32 + lane];
    gather_store(tid, gwv, ca, cidx, abuf[0]);
    __syncthreads();

#pragma unroll 1
    for (int c = 0; c < NCH; c++) {
        bool more = (c + 1) < NCH;
        if (more) {
            gather_load(c + 1, tid, goff, fp2, ca, cidx);
#pragma unroll
            for (int i = 0; i < 4; i++)
                bnext[i] = wB4[((c + 1) * 8 + warp_n * 4 + i) * 32 + lane];
        }

        uint32_t a[2][4];
        uint32_t ab = abase + (c & 1) * (128 * ASTRIDE) +
                      (warp_m * 32 + (lane & 15)) * ASTRIDE + (lane >> 4) * 16;
        ldsm_x4(a[0], ab);
        ldsm_x4(a[1], ab + 16 * ASTRIDE);
#pragma unroll
        for (int nt = 0; nt < 8; nt++) {
            uint32_t b0 = (nt & 1) ? bcur[nt >> 1].z : bcur[nt >> 1].x;
            uint32_t b1 = (nt & 1) ? bcur[nt >> 1].w : bcur[nt >> 1].y;
            mma16816(d[0][nt], a[0], b0, b1);
            mma16816(d[1][nt], a[1], b0, b1);
        }

        if (more) {
            gather_store(tid, gwv, ca, cidx, abuf[(c + 1) & 1]);
#pragma unroll
            for (int i = 0; i < 4; i++) bcur[i] = bnext[i];
        }
        __syncthreads();
    }

    // ---- epilogue: blend + store fp32 + hi/lo bf16 for the conv GEMM ----
#pragma unroll
    for (int mt = 0; mt < 2; mt++) {
#pragma unroll
        for (int rr = 0; rr < 2; rr++) {
            int q = qb + warp_m * 32 + mt * 16 + rr * 8 + (lane >> 2);
            if (q < NPTS) {
#pragma unroll
                for (int nt = 0; nt < 8; nt++) {
                    int o = warp_n * 64 + nt * 8 + 2 * (lane & 3);
                    float2 qv = *(const float2*)&query[(size_t)q * 128 + o];
                    float2 bsv = *(const float2*)&d_bsum[o];
                    float2 r;
                    r.x = 0.025f * d[mt][nt][rr * 2 + 0] + bsv.x + 0.9f * qv.x;
                    r.y = 0.025f * d[mt][nt][rr * 2 + 1] + bsv.y + 0.9f * qv.y;
                    *(float2*)&outq[(size_t)q * 128 + o] = r;
                    uint32_t hi = pack_hi(r.x, r.y);
                    uint32_t lo = pack_lo(r.x, r.y, hi);
                    int ui = q * 64 + (o >> 1);
                    d_nqh[ui] = hi;
                    d_nql[ui] = lo;
                }
            }
        }
    }
}

// ---------------- conv as split-precision bf16 GEMM ----------------
// C[8262,128] = A[8262,1152] @ W'[1152,128] + bias ; A = nq flat (hi+lo bf16)
// block: 64 rows x 128 outs; 8 warps: warp_m = wid&1 (32 rows), warp_n = wid>>1 (32 outs)
__global__ void __launch_bounds__(256) conv2_kernel(const float* __restrict__ conv_b,
                                                    float* __restrict__ nv) {
    __shared__ __align__(16) unsigned char ah[64 * 128];
    __shared__ __align__(16) unsigned char al[64 * 128];

    int tid = threadIdx.x;
    int lane = tid & 31, wid = tid >> 5;
    int warp_m = wid & 1, warp_n = wid >> 1;
    int m0 = blockIdx.x * 64;

    float d[2][4][4];
#pragma unroll
    for (int i = 0; i < 2; i++)
#pragma unroll
        for (int j = 0; j < 4; j++)
#pragma unroll
            for (int k = 0; k < 4; k++) d[i][j][k] = 0.f;

    const uint4* nqh4 = (const uint4*)d_nqh;
    const uint4* nql4 = (const uint4*)d_nql;
    const uint4* cwh4 = (const uint4*)d_cwh;
    const uint4* cwl4 = (const uint4*)d_cwl;
    uint32_t ahb = smem_to_u32(ah);
    uint32_t alb = smem_to_u32(al);

#pragma unroll 1
    for (int it = 0; it < 18; it++) {
        // load A chunk 64 rows x 64 ch (hi + lo), swizzled
        __syncthreads();
#pragma unroll
        for (int j = 0; j < 2; j++) {
            int idx = tid * 2 + j;          // 0..511
            int row = idx >> 3, cu = idx & 7;
            int m = m0 + row;
            int mc = (m < MROWS) ? m : MROWS - 1;
            int g = mc * 144 + it * 8 + cu; // uint4 index
            int soff = row * 128 + ((cu ^ (row & 7)) * 16);
            *(uint4*)(ah + soff) = nqh4[g];
            *(uint4*)(al + soff) = nql4[g];
        }
        __syncthreads();

#pragma unroll
        for (int kt = 0; kt < 4; kt++) {
            int kc = it * 4 + kt;
            uint4 bh0 = cwh4[((kc * 8) + 2 * warp_n + 0) * 32 + lane];
            uint4 bh1 = cwh4[((kc * 8) + 2 * warp_n + 1) * 32 + lane];
            uint4 bl0 = cwl4[((kc * 8) + 2 * warp_n + 0) * 32 + lane];
            uint4 bl1 = cwl4[((kc * 8) + 2 * warp_n + 1) * 32 + lane];
            uint32_t a_h[2][4], a_l[2][4];
#pragma unroll
            for (int mt = 0; mt < 2; mt++) {
                int row = warp_m * 32 + mt * 16 + (lane & 15);
                int cu = kt * 2 + (lane >> 4);
                uint32_t addr = row * 128 + ((cu ^ (row & 7)) * 16);
                ldsm_x4(a_h[mt], ahb + addr);
                ldsm_x4(a_l[mt], alb + addr);
            }
#pragma unroll
            for (int mt = 0; mt < 2; mt++) {
#pragma unroll
                for (int nt = 0; nt < 4; nt++) {
                    uint4 bh = (nt >> 1) ? bh1 : bh0;
                    uint4 bl = (nt >> 1) ? bl1 : bl0;
                    uint32_t bh_0 = (nt & 1) ? bh.z : bh.x;
                    uint32_t bh_1 = (nt & 1) ? bh.w : bh.y;
                    uint32_t bl_0 = (nt & 1) ? bl.z : bl.x;
                    uint32_t bl_1 = (nt & 1) ? bl.w : bl.y;
                    mma16816(d[mt][nt], a_h[mt], bh_0, bh_1);
                    mma16816(d[mt][nt], a_h[mt], bl_0, bl_1);
                    mma16816(d[mt][nt], a_l[mt], bh_0, bh_1);
                }
            }
        }
    }

    // epilogue
#pragma unroll
    for (int mt = 0; mt < 2; mt++) {
#pragma unroll
        for (int rr = 0; rr < 2; rr++) {
            int m = m0 + warp_m * 32 + mt * 16 + rr * 8 + (lane >> 2);
            if (m < MROWS) {
#pragma unroll
                for (int nt = 0; nt < 4; nt++) {
                    int o = warp_n * 32 + nt * 8 + 2 * (lane & 3);
                    float2 cb = *(const float2*)&conv_b[o];
                    float2 r;
                    r.x = d[mt][nt][rr * 2 + 0] + cb.x;
                    r.y = d[mt][nt][rr * 2 + 1] + cb.y;
                    *(float2*)&nv[(size_t)m * 128 + o] = r;
                }
            }
        }
    }
}

// ---------------- launch ----------------
extern "C" void kernel_launch(void* const* d_in, const int* in_sizes, int n_in,
                              void* d_out, int out_size) {
    const float* f0     = (const float*)d_in[0];
    const float* f1     = (const float*)d_in[1];
    const float* f2     = (const float*)d_in[2];
    const float* f3     = (const float*)d_in[3];
    const float* query  = (const float*)d_in[4];
    const float* key    = (const float*)d_in[5];
    const float* value  = (const float*)d_in[6];
    const float* w_off  = (const float*)d_in[7];
    const float* b_off  = (const float*)d_in[8];
    const float* w_attn = (const float*)d_in[9];
    const float* b_attn = (const float*)d_in[10];
    const float* we0    = (const float*)d_in[11];
    const float* be0    = (const float*)d_in[12];
    const float* we1    = (const float*)d_in[13];
    const float* be1    = (const float*)d_in[14];
    const float* we2    = (const float*)d_in[15];
    const float* be2    = (const float*)d_in[16];
    const float* we3    = (const float*)d_in[17];
    const float* be3    = (const float*)d_in[18];
    const float* conv_w = (const float*)d_in[19];
    const float* conv_b = (const float*)d_in[20];

    float* out   = (float*)d_out;
    float* outQ  = out + OUT_Q_OFF;
    float* outV  = out + OUT_V_OFF;
    float* outSP = out + OUT_SP_OFF;

    dim3 tb(32, 8);
    tposef_kernel<<<dim3(3, 2, 18 * 96), tb>>>(f0, 48, 96, 72, FT_OFF0);
    tposef_kernel<<<dim3(2, 3, 18 * 48), tb>>>(f1, 96, 48, 36, FT_OFF1);
    tposef_kernel<<<dim3(1, 6, 18 * 24), tb>>>(f2, 192, 24, 18, FT_OFF2);
    tposef_kernel<<<dim3(1, 12, 18 * 12), tb>>>(f3, 384, 12, 9, FT_OFF3);

    wbfprep_kernel<<<180, 256>>>(we0, we1, we2, we3);
    wcfprep_kernel<<<288, 256>>>(conv_w);
    bsum_kernel<<<1, 128>>>(be0, be1, be2, be3);

    pos_kernel<<<9295, 256>>>(query, key, value, w_off, b_off, w_attn, b_attn, outSP);

    main3_kernel<<<(NPTS + 127) / 128, 256>>>(outSP, query, outQ);

    conv2_kernel<<<(MROWS + 63) / 64, 256>>>(conv_b, outV);
}